// round 9
// baseline (speedup 1.0000x reference)
#include <cuda_runtime.h>
#include <cuda_bf16.h>
#include <cstdint>

// Problem constants
#define BB 4
#define LT 1024
#define LS 1024
#define DD 1024
#define HH 16
#define HD 64
#define FF 4096
#define MTOT (BB*LT)   // 4096 rows

#define SLOT (MTOT*DD)                     // 4M floats
#define WSZ  (DD*DD)                       // 1M floats
#define WBASE ((size_t)5*SLOT + (size_t)MTOT*FF)
__device__ float g_scratch[WBASE + 20*(size_t)WSZ];

// ---------------------------------------------------------------------------
__device__ __forceinline__ uint32_t f2tf32(float f) {
    uint32_t u;
    asm("cvt.rna.tf32.f32 %0, %1;" : "=r"(u) : "f"(f));
    return u;
}
__device__ __forceinline__ float rtf(float f) {
    return __uint_as_float(f2tf32(f));
}

__device__ __forceinline__ void mma_tf32(float* d, const uint32_t* a, const uint32_t* b) {
    asm volatile(
        "mma.sync.aligned.m16n8k8.row.col.f32.tf32.tf32.f32 "
        "{%0,%1,%2,%3}, {%4,%5,%6,%7}, {%8,%9}, {%0,%1,%2,%3};"
        : "+f"(d[0]), "+f"(d[1]), "+f"(d[2]), "+f"(d[3])
        : "r"(a[0]), "r"(a[1]), "r"(a[2]), "r"(a[3]), "r"(b[0]), "r"(b[1]));
}

__device__ __forceinline__ void cp16(uint32_t dst, const float* src) {
    asm volatile("cp.async.cg.shared.global [%0], [%1], 16;" :: "r"(dst), "l"(src));
}

// ldmatrix x4 (b16): tf32 16-bit pairs move intact -> exact tf32 A-fragments.
// Verified correct on HW in R7.
__device__ __forceinline__ void ldsm4(uint32_t* r, uint32_t saddr) {
    asm volatile("ldmatrix.sync.aligned.m8n8.x4.shared.b16 {%0,%1,%2,%3}, [%4];"
        : "=r"(r[0]), "=r"(r[1]), "=r"(r[2]), "=r"(r[3]) : "r"(saddr));
}

// ---------------------------------------------------------------------------
// Elementwise tf32 rounding pass (float4 per thread)
__global__ void round_tf32_kernel(const float4* __restrict__ in,
                                  float4* __restrict__ out)
{
    int idx = blockIdx.x * 256 + threadIdx.x;
    float4 v = in[idx];
    v.x = rtf(v.x); v.y = rtf(v.y); v.z = rtf(v.z); v.w = rtf(v.w);
    out[idx] = v;
}

// ---------------------------------------------------------------------------
// RMSNorm (output rounded to tf32)
__global__ void rmsnorm_kernel(const float* __restrict__ x,
                               const float* __restrict__ g,
                               float* __restrict__ out)
{
    __shared__ float red[256];
    int row = blockIdx.x;
    int tid = threadIdx.x;
    const float4* xr = (const float4*)(x + (size_t)row * DD);
    float4 v = xr[tid];
    float ss = v.x*v.x + v.y*v.y + v.z*v.z + v.w*v.w;
    red[tid] = ss;
    __syncthreads();
    #pragma unroll
    for (int s = 128; s > 0; s >>= 1) {
        if (tid < s) red[tid] += red[tid + s];
        __syncthreads();
    }
    float inv = rsqrtf(red[0] * (1.0f/(float)DD) + 1e-6f);
    const float4 gg = ((const float4*)g)[tid];
    float4 o;
    o.x = rtf(v.x * inv * gg.x);
    o.y = rtf(v.y * inv * gg.y);
    o.z = rtf(v.z * inv * gg.z);
    o.w = rtf(v.w * inv * gg.w);
    ((float4*)(out + (size_t)row * DD))[tid] = o;
}

// ---------------------------------------------------------------------------
// TF32 tensor-core GEMM, 4-stage cp.async pipeline, BK=16, one sync/iter.
// A-fragments via ldmatrix (streamed), B via scalar LDS.
// C[M,N] = A[M,K] @ B[K,N]. Operands pre-rounded to tf32 (raw-bit loads).
// Epilogues: 1 KV-transpose, 2 resid, 3 relu+round, 4 plain+round.
#define TC_BM 128
#define TC_BN 128
#define TC_BK 16
#define AS_STRIDE 28                        // ldmatrix phases 7r mod 8: conflict-free
#define BS_STRIDE (TC_BN + 8)               // 136, proven conflict-free
#define A_STAGE (TC_BM * AS_STRIDE)         // 3584 floats
#define B_STAGE (TC_BK * BS_STRIDE)         // 2176 floats
#define STAGE_ELEMS (A_STAGE + B_STAGE)     // 5760 floats
#define TC_SMEM_BYTES (4 * STAGE_ELEMS * 4) // 92160 B

template<int EPI>
__global__ __launch_bounds__(256)
void tc_gemm(const float* __restrict__ A, const float* __restrict__ B,
             float* __restrict__ C, const float* __restrict__ R,
             int M, int N, int K)
{
    extern __shared__ float sm[];
    const uint32_t smb = (uint32_t)__cvta_generic_to_shared(sm);

    const int tid  = threadIdx.x;
    const int wid  = tid >> 5;
    const int lane = tid & 31;
    const int g    = lane >> 2;
    const int t    = lane & 3;
    const int wm   = wid & 1;
    const int wn   = wid >> 1;
    const int m0   = blockIdx.y * TC_BM;
    const int n0   = blockIdx.x * TC_BN;

    // ldmatrix lane-address components (verified mapping, R7)
    const int fr = (lane & 7) + ((lane >> 3) & 1) * 8;
    const int fk = ((lane >> 4) & 1) * 4;
    // per-thread ldmatrix offset within an A stage (bytes)
    const uint32_t a_lane_off = (uint32_t)(((wm * 64 + fr) * AS_STRIDE + fk) << 2);

    const float* Ag = A + (size_t)m0 * K;
    const float* Bg = B + n0;

    float acc[4][4][4];
    #pragma unroll
    for (int mi = 0; mi < 4; mi++)
        #pragma unroll
        for (int ni = 0; ni < 4; ni++)
            #pragma unroll
            for (int r = 0; r < 4; r++) acc[mi][ni][r] = 0.0f;

    const int NT = K / TC_BK;

    #define G_LOAD(s, k0)                                                     \
    {                                                                         \
        uint32_t ab_ = smb + (uint32_t)((s) * STAGE_ELEMS * 4);               \
        uint32_t bb_ = ab_ + (uint32_t)(A_STAGE * 4);                         \
        _Pragma("unroll")                                                     \
        for (int i_ = 0; i_ < 2; i_++) {                                      \
            int idx_ = tid + i_ * 256;                                        \
            int ar_ = idx_ >> 2, ac_ = (idx_ & 3) * 4;                        \
            cp16(ab_ + (uint32_t)((ar_ * AS_STRIDE + ac_) << 2),              \
                 Ag + (size_t)ar_ * K + (k0) + ac_);                          \
            int br_ = idx_ >> 5, bc_ = (idx_ & 31) * 4;                       \
            cp16(bb_ + (uint32_t)((br_ * BS_STRIDE + bc_) << 2),              \
                 Bg + (size_t)((k0) + br_) * N + bc_);                        \
        }                                                                     \
    }

    // prologue: stages 0,1 in flight
    G_LOAD(0, 0);
    asm volatile("cp.async.commit_group;");
    G_LOAD(1, TC_BK);
    asm volatile("cp.async.commit_group;");

    for (int kt = 0; kt < NT; kt++) {
        if (kt + 2 < NT) {
            G_LOAD((kt + 2) & 3, (kt + 2) * TC_BK);
        }
        asm volatile("cp.async.commit_group;");
        asm volatile("cp.async.wait_group 2;");
        __syncthreads();

        const uint32_t astage = smb + (uint32_t)((kt & 3) * STAGE_ELEMS * 4);
        const uint32_t aaddr  = astage + a_lane_off;
        const float*   Bs     = sm + (kt & 3) * STAGE_ELEMS + A_STAGE;
        const uint32_t* Bb    = (const uint32_t*)(Bs + t * BS_STRIDE + wn * 32 + g);

        #pragma unroll
        for (int kk = 0; kk < 2; kk++) {
            uint32_t bf[4][2];
            #pragma unroll
            for (int ni = 0; ni < 4; ni++) {
                const uint32_t* p = Bb + kk * 8 * BS_STRIDE + ni * 8;
                bf[ni][0] = p[0];
                bf[ni][1] = p[4 * BS_STRIDE];
            }
            #pragma unroll
            for (int mi = 0; mi < 4; mi++) {
                uint32_t af[4];
                ldsm4(af, aaddr + (uint32_t)(((mi * 16 * AS_STRIDE) + kk * 8) << 2));
                #pragma unroll
                for (int ni = 0; ni < 4; ni++)
                    mma_tf32(acc[mi][ni], af, bf[ni]);
            }
        }
    }
    #undef G_LOAD

    const int mbase = m0 + wm * 64 + g;
    const int nbase = n0 + wn * 32 + 2 * t;

    if (EPI == 1) {
        #pragma unroll
        for (int mi = 0; mi < 4; mi++) {
            #pragma unroll
            for (int ni = 0; ni < 4; ni++) {
                #pragma unroll
                for (int half = 0; half < 2; half++) {
                    int m = mbase + mi * 16 + half * 8;
                    int b = m >> 10, l = m & 1023;
                    #pragma unroll
                    for (int c = 0; c < 2; c++) {
                        int n = nbase + ni * 8 + c;
                        int h = n >> 6, d = n & 63;
                        C[(((size_t)(b * HH + h) * LT + l) << 6) + d] =
                            acc[mi][ni][half * 2 + c];
                    }
                }
            }
        }
    } else {
        #pragma unroll
        for (int mi = 0; mi < 4; mi++) {
            #pragma unroll
            for (int ni = 0; ni < 4; ni++) {
                int n = nbase + ni * 8;
                #pragma unroll
                for (int half = 0; half < 2; half++) {
                    int m = mbase + mi * 16 + half * 8;
                    size_t off = (size_t)m * N + n;
                    float2 v = make_float2(acc[mi][ni][half * 2], acc[mi][ni][half * 2 + 1]);
                    if (EPI == 2) {
                        float2 r = *(const float2*)(R + off);
                        v.x += r.x; v.y += r.y;
                    }
                    if (EPI == 3) {
                        v.x = rtf(fmaxf(v.x, 0.f)); v.y = rtf(fmaxf(v.y, 0.f));
                    }
                    if (EPI == 4) {
                        v.x = rtf(v.x); v.y = rtf(v.y);
                    }
                    *(float2*)(C + off) = v;
                }
            }
        }
    }
}

// ---------------------------------------------------------------------------
// Tensor-core flash attention (tf32 mma, online softmax) — R6/R8 proven version.
#define ATT_SMEM0 (26624 * 4)
#define ATT_SMEM1 (35328 * 4)

#define LOAD_TILE(dstoff, srcptr, srcstride, STRIDE)                          \
    _Pragma("unroll")                                                         \
    for (int i_ = 0; i_ < 8; i_++) {                                          \
        int idx_ = tid + i_ * 128;                                            \
        int r_ = idx_ >> 4, c_ = (idx_ & 15) * 4;                             \
        cp16(sbase + (uint32_t)(((dstoff) + r_ * (STRIDE) + c_) << 2),        \
             (srcptr) + (size_t)r_ * (srcstride) + c_);                       \
    }

template<int MODE>
__global__ __launch_bounds__(128)
void attn_tc(const float* __restrict__ Q, const float* __restrict__ K,
             const float* __restrict__ V, const float* __restrict__ bias,
             float* __restrict__ O)
{
    extern __shared__ float smf[];
    const int tid  = threadIdx.x;
    const int wid  = tid >> 5;
    const int lane = tid & 31;
    const int g    = lane >> 2;
    const int t    = lane & 3;
    const int qt   = blockIdx.x;
    const int h    = blockIdx.y;
    const int b    = blockIdx.z;

    const uint32_t sbase = (uint32_t)__cvta_generic_to_shared(smf);

    const float* Qg = Q + ((size_t)(b * LT) + qt * 64) * DD + h * HD;
    const float* Kg = K + ((size_t)(b * HH + h)) * LS * HD;
    const float* Vg = V + ((size_t)(b * HH + h)) * LS * HD;
    const float* Bg = (MODE == 1) ? bias + ((size_t)h * LT + qt * 64) * LS : nullptr;

    {
        LOAD_TILE(0,     Qg, DD, 68);
        LOAD_TILE(4352,  Kg, HD, 68);
        LOAD_TILE(13056, Vg, HD, 72);
        if (MODE == 1) {
            LOAD_TILE(26624, Bg, LS, 68);
        }
        asm volatile("cp.async.commit_group;");
    }

    float oacc[8][4];
    #pragma unroll
    for (int ni = 0; ni < 8; ni++)
        #pragma unroll
        for (int r = 0; r < 4; r++) oacc[ni][r] = 0.0f;

    float mrow[2] = { -1e30f, -1e30f };
    float lrow[2] = { 0.0f, 0.0f };

    const int ktmax = (MODE == 0) ? qt : (LS / 64 - 1);

    for (int kt = 0; kt <= ktmax; kt++) {
        const int cur = kt & 1;
        __syncthreads();
        if (kt + 1 <= ktmax) {
            const int nk = kt + 1;
            const uint32_t koff = (cur == 0) ? 8704u  : 4352u;
            const uint32_t voff = (cur == 0) ? 17664u : 13056u;
            const float* kp = Kg + (size_t)nk * 64 * HD;
            const float* vp = Vg + (size_t)nk * 64 * HD;
            LOAD_TILE(koff, kp, HD, 68);
            LOAD_TILE(voff, vp, HD, 72);
            if (MODE == 1) {
                const uint32_t boff = (cur == 0) ? 30976u : 26624u;
                const float* bp = Bg + (size_t)nk * 64;
                LOAD_TILE(boff, bp, LS, 68);
            }
            asm volatile("cp.async.commit_group;");
            asm volatile("cp.async.wait_group 1;");
        } else {
            asm volatile("cp.async.wait_group 0;");
        }
        __syncthreads();

        const float* Ksc = smf + (cur ? 8704 : 4352);
        const float* Vsc = smf + (cur ? 17664 : 13056);
        const float* Bic = smf + (cur ? 30976 : 26624);

        // ---- S = Q K^T ----
        float sacc[8][4];
        #pragma unroll
        for (int ni = 0; ni < 8; ni++)
            #pragma unroll
            for (int r = 0; r < 4; r++) sacc[ni][r] = 0.0f;

        {
            const uint32_t* qb = (const uint32_t*)(smf + (wid * 16 + g) * 68 + t);
            const float* kb = Ksc + g * 68 + t;
            #pragma unroll
            for (int kk = 0; kk < 8; kk++) {
                uint32_t a[4];
                a[0] = qb[kk * 8];
                a[1] = qb[8 * 68 + kk * 8];
                a[2] = qb[kk * 8 + 4];
                a[3] = qb[8 * 68 + kk * 8 + 4];
                #pragma unroll
                for (int ni = 0; ni < 8; ni++) {
                    uint32_t bf[2];
                    bf[0] = f2tf32(kb[ni * 8 * 68 + kk * 8]);
                    bf[1] = f2tf32(kb[ni * 8 * 68 + kk * 8 + 4]);
                    mma_tf32(sacc[ni], a, bf);
                }
            }
        }

        // ---- softmax ----
        uint32_t* Psu = (uint32_t*)(smf + 22272);
        #pragma unroll
        for (int half = 0; half < 2; half++) {
            const int row_l = wid * 16 + g + half * 8;
            float mx = -1e30f;
            #pragma unroll
            for (int ni = 0; ni < 8; ni++) {
                #pragma unroll
                for (int c = 0; c < 2; c++) {
                    float v = sacc[ni][half * 2 + c] * 0.125f;
                    if (MODE == 0) {
                        if (kt == qt) {
                            int keyl = ni * 8 + 2 * t + c;
                            if (keyl > row_l) v = -1e30f;
                        }
                    } else {
                        v += Bic[row_l * 68 + ni * 8 + 2 * t + c];
                    }
                    sacc[ni][half * 2 + c] = v;
                    mx = fmaxf(mx, v);
                }
            }
            mx = fmaxf(mx, __shfl_xor_sync(0xffffffffu, mx, 1));
            mx = fmaxf(mx, __shfl_xor_sync(0xffffffffu, mx, 2));
            float mnew = fmaxf(mrow[half], mx);
            float corr = __expf(mrow[half] - mnew);
            mrow[half] = mnew;
            float sum = 0.0f;
            #pragma unroll
            for (int ni = 0; ni < 8; ni++) {
                float p0 = __expf(sacc[ni][half * 2]     - mnew);
                float p1 = __expf(sacc[ni][half * 2 + 1] - mnew);
                sum += p0 + p1;
                sacc[ni][half * 2]     = p0;
                sacc[ni][half * 2 + 1] = p1;
            }
            sum += __shfl_xor_sync(0xffffffffu, sum, 1);
            sum += __shfl_xor_sync(0xffffffffu, sum, 2);
            lrow[half] = lrow[half] * corr + sum;
            #pragma unroll
            for (int ni = 0; ni < 8; ni++) {
                oacc[ni][half * 2]     *= corr;
                oacc[ni][half * 2 + 1] *= corr;
                uint2 pp = make_uint2(f2tf32(sacc[ni][half * 2]),
                                      f2tf32(sacc[ni][half * 2 + 1]));
                *(uint2*)&Psu[row_l * 68 + ni * 8 + 2 * t] = pp;
            }
        }
        __syncwarp();

        // ---- O += P V ----
        {
            const uint32_t* pb = Psu + (wid * 16 + g) * 68 + t;
            const float* vb = Vsc + t * 72 + g;
            #pragma unroll
            for (int kk = 0; kk < 8; kk++) {
                uint32_t a[4];
                a[0] = pb[kk * 8];
                a[1] = pb[8 * 68 + kk * 8];
                a[2] = pb[kk * 8 + 4];
                a[3] = pb[8 * 68 + kk * 8 + 4];
                #pragma unroll
                for (int ni = 0; ni < 8; ni++) {
                    uint32_t bf[2];
                    bf[0] = f2tf32(vb[kk * 8 * 72 + ni * 8]);
                    bf[1] = f2tf32(vb[kk * 8 * 72 + 4 * 72 + ni * 8]);
                    mma_tf32(oacc[ni], a, bf);
                }
            }
        }
        __syncwarp();
    }

    // ---- normalize + write O (rounded: feeds GEMM A) ----
    #pragma unroll
    for (int half = 0; half < 2; half++) {
        const int row_l = wid * 16 + g + half * 8;
        const int qg = qt * 64 + row_l;
        const float invl = 1.0f / lrow[half];
        float* op = O + ((size_t)(b * LT) + qg) * DD + h * HD;
        #pragma unroll
        for (int ni = 0; ni < 8; ni++) {
            float2 v = make_float2(rtf(oacc[ni][half * 2] * invl),
                                   rtf(oacc[ni][half * 2 + 1] * invl));
            *(float2*)(op + ni * 8 + 2 * t) = v;
        }
    }
}

// ---------------------------------------------------------------------------
extern "C" void kernel_launch(void* const* d_in, const int* in_sizes, int n_in,
                              void* d_out, int out_size)
{
    const float* x        = (const float*)d_in[0];
    const float* memory   = (const float*)d_in[1];
    const float* pos_emb  = (const float*)d_in[2];
    const float* gamma_sa = (const float*)d_in[4];
    const float* wq_s     = (const float*)d_in[5];
    const float* wk_s     = (const float*)d_in[6];
    const float* wv_s     = (const float*)d_in[7];
    const float* wo_s     = (const float*)d_in[8];
    const float* gamma_ca = (const float*)d_in[9];
    const float* wq_c     = (const float*)d_in[10];
    const float* wk_c     = (const float*)d_in[11];
    const float* wv_c     = (const float*)d_in[12];
    const float* wo_c     = (const float*)d_in[13];
    const float* gamma_m  = (const float*)d_in[14];
    const float* w1       = (const float*)d_in[15];
    const float* w2       = (const float*)d_in[16];

    float* scratch = nullptr;
    cudaGetSymbolAddress((void**)&scratch, g_scratch);
    float* bh    = scratch;
    float* bq    = scratch + (size_t)1 * SLOT;
    float* battn = scratch + (size_t)2 * SLOT;
    float* bx1   = scratch + (size_t)3 * SLOT;
    float* bx2   = scratch + (size_t)4 * SLOT;
    float* bffn  = scratch + (size_t)5 * SLOT;
    float* wbase = scratch + WBASE;
    float* rwq_s = wbase + 0 * (size_t)WSZ;
    float* rwk_s = wbase + 1 * (size_t)WSZ;
    float* rwv_s = wbase + 2 * (size_t)WSZ;
    float* rwo_s = wbase + 3 * (size_t)WSZ;
    float* rwq_c = wbase + 4 * (size_t)WSZ;
    float* rwk_c = wbase + 5 * (size_t)WSZ;
    float* rwv_c = wbase + 6 * (size_t)WSZ;
    float* rwo_c = wbase + 7 * (size_t)WSZ;
    float* rw1   = wbase + 8 * (size_t)WSZ;    // 4*WSZ
    float* rw2   = wbase + 12 * (size_t)WSZ;   // 4*WSZ
    float* rmem  = wbase + 16 * (size_t)WSZ;   // 4*WSZ

    float* out   = (float*)d_out;
    float* o_mlp = out;
    float* o_ks  = out + (size_t)1 * SLOT;
    float* o_vs  = out + (size_t)2 * SLOT;
    float* o_kc  = out + (size_t)3 * SLOT;
    float* o_vc  = out + (size_t)4 * SLOT;

    cudaFuncSetAttribute(tc_gemm<1>, cudaFuncAttributeMaxDynamicSharedMemorySize, TC_SMEM_BYTES);
    cudaFuncSetAttribute(tc_gemm<2>, cudaFuncAttributeMaxDynamicSharedMemorySize, TC_SMEM_BYTES);
    cudaFuncSetAttribute(tc_gemm<3>, cudaFuncAttributeMaxDynamicSharedMemorySize, TC_SMEM_BYTES);
    cudaFuncSetAttribute(tc_gemm<4>, cudaFuncAttributeMaxDynamicSharedMemorySize, TC_SMEM_BYTES);
    cudaFuncSetAttribute(attn_tc<0>, cudaFuncAttributeMaxDynamicSharedMemorySize, ATT_SMEM0);
    cudaFuncSetAttribute(attn_tc<1>, cudaFuncAttributeMaxDynamicSharedMemorySize, ATT_SMEM1);

    // ---- tf32 rounding passes (weights + memory) ----
    #define RND(src, dst, nfloats) \
        round_tf32_kernel<<<(nfloats)/4/256, 256>>>((const float4*)(src), (float4*)(dst))
    RND(wq_s, rwq_s, WSZ); RND(wk_s, rwk_s, WSZ);
    RND(wv_s, rwv_s, WSZ); RND(wo_s, rwo_s, WSZ);
    RND(wq_c, rwq_c, WSZ); RND(wk_c, rwk_c, WSZ);
    RND(wv_c, rwv_c, WSZ); RND(wo_c, rwo_c, WSZ);
    RND(w1, rw1, 4*WSZ);   RND(w2, rw2, 4*WSZ);
    RND(memory, rmem, 4*WSZ);
    #undef RND

    const dim3 gD(DD / TC_BN, MTOT / TC_BM);   // (8, 32)
    const dim3 gF(FF / TC_BN, MTOT / TC_BM);   // (32, 32)
    const dim3 gA(LT / 64, HH, BB);

    // ---- self-attention block ----
    rmsnorm_kernel<<<MTOT, 256>>>(x, gamma_sa, bh);
    tc_gemm<4><<<gD, 256, TC_SMEM_BYTES>>>(bh, rwq_s, bq,   nullptr, MTOT, DD, DD);
    tc_gemm<1><<<gD, 256, TC_SMEM_BYTES>>>(bh, rwk_s, o_ks, nullptr, MTOT, DD, DD);
    tc_gemm<1><<<gD, 256, TC_SMEM_BYTES>>>(bh, rwv_s, o_vs, nullptr, MTOT, DD, DD);
    attn_tc<0><<<gA, 128, ATT_SMEM0>>>(bq, o_ks, o_vs, nullptr, battn);
    tc_gemm<2><<<gD, 256, TC_SMEM_BYTES>>>(battn, rwo_s, bx1, x, MTOT, DD, DD);

    // ---- cross-attention block ----
    rmsnorm_kernel<<<MTOT, 256>>>(bx1, gamma_ca, bh);
    tc_gemm<4><<<gD, 256, TC_SMEM_BYTES>>>(bh,   rwq_c, bq,   nullptr, MTOT, DD, DD);
    tc_gemm<1><<<gD, 256, TC_SMEM_BYTES>>>(rmem, rwk_c, o_kc, nullptr, MTOT, DD, DD);
    tc_gemm<1><<<gD, 256, TC_SMEM_BYTES>>>(rmem, rwv_c, o_vc, nullptr, MTOT, DD, DD);
    attn_tc<1><<<gA, 128, ATT_SMEM1>>>(bq, o_kc, o_vc, pos_emb, battn);
    tc_gemm<2><<<gD, 256, TC_SMEM_BYTES>>>(battn, rwo_c, bx2, bx1, MTOT, DD, DD);

    // ---- FFN block ----
    rmsnorm_kernel<<<MTOT, 256>>>(bx2, gamma_m, bh);
    tc_gemm<3><<<gF, 256, TC_SMEM_BYTES>>>(bh,   rw1, bffn,  nullptr, MTOT, FF, DD);
    tc_gemm<2><<<gD, 256, TC_SMEM_BYTES>>>(bffn, rw2, o_mlp, bx2,     MTOT, DD, FF);
}

// round 11
// speedup vs baseline: 1.4341x; 1.4341x over previous
#include <cuda_runtime.h>
#include <cuda_fp16.h>
#include <cstdint>

// Problem constants
#define BB 4
#define LT 1024
#define LS 1024
#define DD 1024
#define HH 16
#define HD 64
#define FF 4096
#define MTOT (BB*LT)   // 4096 rows

#define SLOT (MTOT*DD)                     // 4M floats
#define WSZ  (DD*DD)                       // 1M floats
// scratch float-slot layout (half buffers under-use their slot):
//   [0..5)*SLOT : bh(half), bq(f32), battn(half), bx1(f32), bx2(f32)
//   5*SLOT      : bffn (half, MTOT*FF)
//   WBASE+...   : half weightsT + half memory
#define WBASE ((size_t)5*SLOT + (size_t)MTOT*FF)
__device__ float g_scratch[WBASE + 20*(size_t)WSZ];

// ---------------------------------------------------------------------------
__device__ __forceinline__ uint32_t f2tf32(float f) {
    uint32_t u;
    asm("cvt.rna.tf32.f32 %0, %1;" : "=r"(u) : "f"(f));
    return u;
}
__device__ __forceinline__ float rtf(float f) {
    return __uint_as_float(f2tf32(f));
}

__device__ __forceinline__ void mma_tf32(float* d, const uint32_t* a, const uint32_t* b) {
    asm volatile(
        "mma.sync.aligned.m16n8k8.row.col.f32.tf32.tf32.f32 "
        "{%0,%1,%2,%3}, {%4,%5,%6,%7}, {%8,%9}, {%0,%1,%2,%3};"
        : "+f"(d[0]), "+f"(d[1]), "+f"(d[2]), "+f"(d[3])
        : "r"(a[0]), "r"(a[1]), "r"(a[2]), "r"(a[3]), "r"(b[0]), "r"(b[1]));
}

__device__ __forceinline__ void mma_f16(float* d, const uint32_t* a, const uint32_t* b) {
    asm volatile(
        "mma.sync.aligned.m16n8k16.row.col.f32.f16.f16.f32 "
        "{%0,%1,%2,%3}, {%4,%5,%6,%7}, {%8,%9}, {%0,%1,%2,%3};"
        : "+f"(d[0]), "+f"(d[1]), "+f"(d[2]), "+f"(d[3])
        : "r"(a[0]), "r"(a[1]), "r"(a[2]), "r"(a[3]), "r"(b[0]), "r"(b[1]));
}

__device__ __forceinline__ void cp16(uint32_t dst, const void* src) {
    asm volatile("cp.async.cg.shared.global [%0], [%1], 16;" :: "r"(dst), "l"(src));
}

// ---------------------------------------------------------------------------
// Preprocess: fp32 -> fp16 elementwise
__global__ void f32_to_f16(const float4* __restrict__ in, __half2* __restrict__ out)
{
    int idx = blockIdx.x * 256 + threadIdx.x;
    float4 v = in[idx];
    out[idx * 2]     = __floats2half2_rn(v.x, v.y);
    out[idx * 2 + 1] = __floats2half2_rn(v.z, v.w);
}

// Preprocess: transpose + fp16: in[K][N] f32 -> out[N][K] half
__global__ void xpose_f16(const float* __restrict__ in, __half* __restrict__ out,
                          int K, int N)
{
    __shared__ float t[32][33];
    int n0 = blockIdx.x * 32, k0 = blockIdx.y * 32;
    int tx = threadIdx.x, ty = threadIdx.y;   // 32 x 8
    #pragma unroll
    for (int i = 0; i < 4; i++)
        t[ty + i * 8][tx] = in[(size_t)(k0 + ty + i * 8) * N + n0 + tx];
    __syncthreads();
    #pragma unroll
    for (int i = 0; i < 4; i++)
        out[(size_t)(n0 + ty + i * 8) * K + k0 + tx] = __float2half_rn(t[tx][ty + i * 8]);
}

// ---------------------------------------------------------------------------
// RMSNorm: fp32 in -> fp16 out (GEMM A operand)
__global__ void rmsnorm_kernel(const float* __restrict__ x,
                               const float* __restrict__ g,
                               __half2* __restrict__ out)
{
    __shared__ float red[256];
    int row = blockIdx.x;
    int tid = threadIdx.x;
    const float4* xr = (const float4*)(x + (size_t)row * DD);
    float4 v = xr[tid];
    float ss = v.x*v.x + v.y*v.y + v.z*v.z + v.w*v.w;
    red[tid] = ss;
    __syncthreads();
    #pragma unroll
    for (int s = 128; s > 0; s >>= 1) {
        if (tid < s) red[tid] += red[tid + s];
        __syncthreads();
    }
    float inv = rsqrtf(red[0] * (1.0f/(float)DD) + 1e-6f);
    const float4 gg = ((const float4*)g)[tid];
    __half2* op = out + (size_t)row * (DD/2);
    op[tid * 2]     = __floats2half2_rn(v.x * inv * gg.x, v.y * inv * gg.y);
    op[tid * 2 + 1] = __floats2half2_rn(v.z * inv * gg.z, v.w * inv * gg.w);
}

// ---------------------------------------------------------------------------
// FP16 tensor-core GEMM: C[M,N](f32) = A[M,K](f16) @ BT[N,K](f16)^T.
// 128x128 tile, BK=32 halves, 4-stage cp.async ring, one sync/iter (R8-proven).
// Epilogues: 1 KV(f32), 2 resid(f32), 3 relu(->half), 4 plain tf32-round(f32).
#define TC_BK 32                             // halves per stage
#define AW 20                                // row stride in 32-bit words (16+4 pad)
#define TILE_W (128 * AW)                    // words per operand stage
#define STAGE_W (2 * TILE_W)                 // 5120 words
#define TC_SMEM_BYTES (4 * STAGE_W * 4)      // 81920 B

template<int EPI>
__global__ __launch_bounds__(256)
void tc_gemm(const __half* __restrict__ A, const __half* __restrict__ BT,
             float* __restrict__ C, const float* __restrict__ R,
             int M, int N, int K)
{
    extern __shared__ float sm[];
    const uint32_t smb = (uint32_t)__cvta_generic_to_shared(sm);

    const int tid  = threadIdx.x;
    const int wid  = tid >> 5;
    const int lane = tid & 31;
    const int g    = lane >> 2;
    const int t    = lane & 3;
    const int wm   = wid & 1;
    const int wn   = wid >> 1;
    const int m0   = blockIdx.y * 128;
    const int n0   = blockIdx.x * 128;

    const __half* Ag = A  + (size_t)m0 * K;
    const __half* Bg = BT + (size_t)n0 * K;

    float acc[4][4][4];
    #pragma unroll
    for (int mi = 0; mi < 4; mi++)
        #pragma unroll
        for (int ni = 0; ni < 4; ni++)
            #pragma unroll
            for (int r = 0; r < 4; r++) acc[mi][ni][r] = 0.0f;

    const int NT = K / TC_BK;

    // stage loader: A 512 + B 512 16B-chunks, 2+2 per thread
    #define G_LOAD(s, k0)                                                     \
    {                                                                         \
        uint32_t ab_ = smb + (uint32_t)((s) * STAGE_W * 4);                   \
        uint32_t bb_ = ab_ + (uint32_t)(TILE_W * 4);                          \
        _Pragma("unroll")                                                     \
        for (int i_ = 0; i_ < 2; i_++) {                                      \
            int idx_ = tid + i_ * 256;                                        \
            int r_ = idx_ >> 2, c_ = idx_ & 3;                                \
            cp16(ab_ + (uint32_t)((r_ * AW + c_ * 4) << 2),                   \
                 Ag + (size_t)r_ * K + (k0) + c_ * 8);                        \
            cp16(bb_ + (uint32_t)((r_ * AW + c_ * 4) << 2),                   \
                 Bg + (size_t)r_ * K + (k0) + c_ * 8);                        \
        }                                                                     \
    }

    G_LOAD(0, 0);
    asm volatile("cp.async.commit_group;");
    G_LOAD(1, TC_BK);
    asm volatile("cp.async.commit_group;");

    for (int kt = 0; kt < NT; kt++) {
        if (kt + 2 < NT) {
            G_LOAD((kt + 2) & 3, (kt + 2) * TC_BK);
        }
        asm volatile("cp.async.commit_group;");
        asm volatile("cp.async.wait_group 2;");
        __syncthreads();

        const uint32_t* As = (const uint32_t*)sm + (kt & 3) * STAGE_W;
        const uint32_t* Bs = As + TILE_W;
        const uint32_t* Ab = As + (wm * 64 + g) * AW + t;
        const uint32_t* Bb = Bs + (wn * 32 + g) * AW + t;

        #pragma unroll
        for (int kk = 0; kk < 2; kk++) {
            uint32_t af[4][4];
            uint32_t bf[4][2];
            #pragma unroll
            for (int mi = 0; mi < 4; mi++) {
                const uint32_t* p = Ab + mi * 16 * AW + kk * 8;
                af[mi][0] = p[0];
                af[mi][1] = p[8 * AW];
                af[mi][2] = p[4];
                af[mi][3] = p[8 * AW + 4];
            }
            #pragma unroll
            for (int ni = 0; ni < 4; ni++) {
                const uint32_t* p = Bb + ni * 8 * AW + kk * 8;
                bf[ni][0] = p[0];
                bf[ni][1] = p[4];
            }
            #pragma unroll
            for (int mi = 0; mi < 4; mi++)
                #pragma unroll
                for (int ni = 0; ni < 4; ni++)
                    mma_f16(acc[mi][ni], af[mi], bf[ni]);
        }
    }
    #undef G_LOAD

    const int mbase = m0 + wm * 64 + g;
    const int nbase = n0 + wn * 32 + 2 * t;

    if (EPI == 1) {
        #pragma unroll
        for (int mi = 0; mi < 4; mi++) {
            #pragma unroll
            for (int ni = 0; ni < 4; ni++) {
                #pragma unroll
                for (int half_ = 0; half_ < 2; half_++) {
                    int m = mbase + mi * 16 + half_ * 8;
                    int b = m >> 10, l = m & 1023;
                    #pragma unroll
                    for (int c = 0; c < 2; c++) {
                        int n = nbase + ni * 8 + c;
                        int h = n >> 6, d = n & 63;
                        C[(((size_t)(b * HH + h) * LT + l) << 6) + d] =
                            acc[mi][ni][half_ * 2 + c];
                    }
                }
            }
        }
    } else if (EPI == 3) {
        __half* Ch = (__half*)C;
        #pragma unroll
        for (int mi = 0; mi < 4; mi++) {
            #pragma unroll
            for (int ni = 0; ni < 4; ni++) {
                int n = nbase + ni * 8;
                #pragma unroll
                for (int half_ = 0; half_ < 2; half_++) {
                    int m = mbase + mi * 16 + half_ * 8;
                    size_t off = (size_t)m * N + n;
                    __half2 hv = __floats2half2_rn(
                        fmaxf(acc[mi][ni][half_ * 2],     0.f),
                        fmaxf(acc[mi][ni][half_ * 2 + 1], 0.f));
                    *(__half2*)(Ch + off) = hv;
                }
            }
        }
    } else {
        #pragma unroll
        for (int mi = 0; mi < 4; mi++) {
            #pragma unroll
            for (int ni = 0; ni < 4; ni++) {
                int n = nbase + ni * 8;
                #pragma unroll
                for (int half_ = 0; half_ < 2; half_++) {
                    int m = mbase + mi * 16 + half_ * 8;
                    size_t off = (size_t)m * N + n;
                    float2 v = make_float2(acc[mi][ni][half_ * 2], acc[mi][ni][half_ * 2 + 1]);
                    if (EPI == 2) {
                        float2 r = *(const float2*)(R + off);
                        v.x += r.x; v.y += r.y;
                    }
                    if (EPI == 4) {
                        v.x = rtf(v.x); v.y = rtf(v.y);
                    }
                    *(float2*)(C + off) = v;
                }
            }
        }
    }
}

// ---------------------------------------------------------------------------
// Tensor-core flash attention (tf32 mma, online softmax) — R8-proven core.
// Q (fp32, tf32-rounded) raw loads; K/V fp32 cvt at frag load; output -> half.
#define ATT_SMEM0 (26624 * 4)
#define ATT_SMEM1 (35328 * 4)

#define LOAD_TILE(dstoff, srcptr, srcstride, STRIDE)                          \
    _Pragma("unroll")                                                         \
    for (int i_ = 0; i_ < 8; i_++) {                                          \
        int idx_ = tid + i_ * 128;                                            \
        int r_ = idx_ >> 4, c_ = (idx_ & 15) * 4;                             \
        cp16(sbase + (uint32_t)(((dstoff) + r_ * (STRIDE) + c_) << 2),        \
             (srcptr) + (size_t)r_ * (srcstride) + c_);                       \
    }

template<int MODE>
__global__ __launch_bounds__(128)
void attn_tc(const float* __restrict__ Q, const float* __restrict__ K,
             const float* __restrict__ V, const float* __restrict__ bias,
             __half* __restrict__ O)
{
    extern __shared__ float smf[];
    const int tid  = threadIdx.x;
    const int wid  = tid >> 5;
    const int lane = tid & 31;
    const int g    = lane >> 2;
    const int t    = lane & 3;
    const int qt   = blockIdx.x;
    const int h    = blockIdx.y;
    const int b    = blockIdx.z;

    const uint32_t sbase = (uint32_t)__cvta_generic_to_shared(smf);

    const float* Qg = Q + ((size_t)(b * LT) + qt * 64) * DD + h * HD;
    const float* Kg = K + ((size_t)(b * HH + h)) * LS * HD;
    const float* Vg = V + ((size_t)(b * HH + h)) * LS * HD;
    const float* Bg = (MODE == 1) ? bias + ((size_t)h * LT + qt * 64) * LS : nullptr;

    {
        LOAD_TILE(0,     Qg, DD, 68);
        LOAD_TILE(4352,  Kg, HD, 68);
        LOAD_TILE(13056, Vg, HD, 72);
        if (MODE == 1) {
            LOAD_TILE(26624, Bg, LS, 68);
        }
        asm volatile("cp.async.commit_group;");
    }

    float oacc[8][4];
    #pragma unroll
    for (int ni = 0; ni < 8; ni++)
        #pragma unroll
        for (int r = 0; r < 4; r++) oacc[ni][r] = 0.0f;

    float mrow[2] = { -1e30f, -1e30f };
    float lrow[2] = { 0.0f, 0.0f };

    const int ktmax = (MODE == 0) ? qt : (LS / 64 - 1);

    for (int kt = 0; kt <= ktmax; kt++) {
        const int cur = kt & 1;
        __syncthreads();
        if (kt + 1 <= ktmax) {
            const int nk = kt + 1;
            const uint32_t koff = (cur == 0) ? 8704u  : 4352u;
            const uint32_t voff = (cur == 0) ? 17664u : 13056u;
            const float* kp = Kg + (size_t)nk * 64 * HD;
            const float* vp = Vg + (size_t)nk * 64 * HD;
            LOAD_TILE(koff, kp, HD, 68);
            LOAD_TILE(voff, vp, HD, 72);
            if (MODE == 1) {
                const uint32_t boff = (cur == 0) ? 30976u : 26624u;
                const float* bp = Bg + (size_t)nk * 64;
                LOAD_TILE(boff, bp, LS, 68);
            }
            asm volatile("cp.async.commit_group;");
            asm volatile("cp.async.wait_group 1;");
        } else {
            asm volatile("cp.async.wait_group 0;");
        }
        __syncthreads();

        const float* Ksc = smf + (cur ? 8704 : 4352);
        const float* Vsc = smf + (cur ? 17664 : 13056);
        const float* Bic = smf + (cur ? 30976 : 26624);

        // ---- S = Q K^T ----
        float sacc[8][4];
        #pragma unroll
        for (int ni = 0; ni < 8; ni++)
            #pragma unroll
            for (int r = 0; r < 4; r++) sacc[ni][r] = 0.0f;

        {
            const uint32_t* qb = (const uint32_t*)(smf + (wid * 16 + g) * 68 + t);
            const float* kb = Ksc + g * 68 + t;
            #pragma unroll
            for (int kk = 0; kk < 8; kk++) {
                uint32_t a[4];
                a[0] = qb[kk * 8];
                a[1] = qb[8 * 68 + kk * 8];
                a[2] = qb[kk * 8 + 4];
                a[3] = qb[8 * 68 + kk * 8 + 4];
                #pragma unroll
                for (int ni = 0; ni < 8; ni++) {
                    uint32_t bf[2];
                    bf[0] = f2tf32(kb[ni * 8 * 68 + kk * 8]);
                    bf[1] = f2tf32(kb[ni * 8 * 68 + kk * 8 + 4]);
                    mma_tf32(sacc[ni], a, bf);
                }
            }
        }

        // ---- softmax ----
        uint32_t* Psu = (uint32_t*)(smf + 22272);
        #pragma unroll
        for (int half_ = 0; half_ < 2; half_++) {
            const int row_l = wid * 16 + g + half_ * 8;
            float mx = -1e30f;
            #pragma unroll
            for (int ni = 0; ni < 8; ni++) {
                #pragma unroll
                for (int c = 0; c < 2; c++) {
                    float v = sacc[ni][half_ * 2 + c] * 0.125f;
                    if (MODE == 0) {
                        if (kt == qt) {
                            int keyl = ni * 8 + 2 * t + c;
                            if (keyl > row_l) v = -1e30f;
                        }
                    } else {
                        v += Bic[row_l * 68 + ni * 8 + 2 * t + c];
                    }
                    sacc[ni][half_ * 2 + c] = v;
                    mx = fmaxf(mx, v);
                }
            }
            mx = fmaxf(mx, __shfl_xor_sync(0xffffffffu, mx, 1));
            mx = fmaxf(mx, __shfl_xor_sync(0xffffffffu, mx, 2));
            float mnew = fmaxf(mrow[half_], mx);
            float corr = __expf(mrow[half_] - mnew);
            mrow[half_] = mnew;
            float sum = 0.0f;
            #pragma unroll
            for (int ni = 0; ni < 8; ni++) {
                float p0 = __expf(sacc[ni][half_ * 2]     - mnew);
                float p1 = __expf(sacc[ni][half_ * 2 + 1] - mnew);
                sum += p0 + p1;
                sacc[ni][half_ * 2]     = p0;
                sacc[ni][half_ * 2 + 1] = p1;
            }
            sum += __shfl_xor_sync(0xffffffffu, sum, 1);
            sum += __shfl_xor_sync(0xffffffffu, sum, 2);
            lrow[half_] = lrow[half_] * corr + sum;
            #pragma unroll
            for (int ni = 0; ni < 8; ni++) {
                oacc[ni][half_ * 2]     *= corr;
                oacc[ni][half_ * 2 + 1] *= corr;
                uint2 pp = make_uint2(f2tf32(sacc[ni][half_ * 2]),
                                      f2tf32(sacc[ni][half_ * 2 + 1]));
                *(uint2*)&Psu[row_l * 68 + ni * 8 + 2 * t] = pp;
            }
        }
        __syncwarp();

        // ---- O += P V ----
        {
            const uint32_t* pb = Psu + (wid * 16 + g) * 68 + t;
            const float* vb = Vsc + t * 72 + g;
            #pragma unroll
            for (int kk = 0; kk < 8; kk++) {
                uint32_t a[4];
                a[0] = pb[kk * 8];
                a[1] = pb[8 * 68 + kk * 8];
                a[2] = pb[kk * 8 + 4];
                a[3] = pb[8 * 68 + kk * 8 + 4];
                #pragma unroll
                for (int ni = 0; ni < 8; ni++) {
                    uint32_t bf[2];
                    bf[0] = f2tf32(vb[kk * 8 * 72 + ni * 8]);
                    bf[1] = f2tf32(vb[kk * 8 * 72 + 4 * 72 + ni * 8]);
                    mma_tf32(oacc[ni], a, bf);
                }
            }
        }
        __syncwarp();
    }

    // ---- normalize + write O as fp16 (feeds GEMM A) ----
    #pragma unroll
    for (int half_ = 0; half_ < 2; half_++) {
        const int row_l = wid * 16 + g + half_ * 8;
        const int qg = qt * 64 + row_l;
        const float invl = 1.0f / lrow[half_];
        __half* op = O + ((size_t)(b * LT) + qg) * DD + h * HD;
        #pragma unroll
        for (int ni = 0; ni < 8; ni++) {
            __half2 hv = __floats2half2_rn(oacc[ni][half_ * 2] * invl,
                                           oacc[ni][half_ * 2 + 1] * invl);
            *(__half2*)(op + ni * 8 + 2 * t) = hv;
        }
    }
}

// ---------------------------------------------------------------------------
extern "C" void kernel_launch(void* const* d_in, const int* in_sizes, int n_in,
                              void* d_out, int out_size)
{
    const float* x        = (const float*)d_in[0];
    const float* memory   = (const float*)d_in[1];
    const float* pos_emb  = (const float*)d_in[2];
    const float* gamma_sa = (const float*)d_in[4];
    const float* wq_s     = (const float*)d_in[5];
    const float* wk_s     = (const float*)d_in[6];
    const float* wv_s     = (const float*)d_in[7];
    const float* wo_s     = (const float*)d_in[8];
    const float* gamma_ca = (const float*)d_in[9];
    const float* wq_c     = (const float*)d_in[10];
    const float* wk_c     = (const float*)d_in[11];
    const float* wv_c     = (const float*)d_in[12];
    const float* wo_c     = (const float*)d_in[13];
    const float* gamma_m  = (const float*)d_in[14];
    const float* w1       = (const float*)d_in[15];
    const float* w2       = (const float*)d_in[16];

    float* scratch = nullptr;
    cudaGetSymbolAddress((void**)&scratch, g_scratch);
    __half* bh    = (__half*)(scratch);
    float*  bq    = scratch + (size_t)1 * SLOT;
    __half* battn = (__half*)(scratch + (size_t)2 * SLOT);
    float*  bx1   = scratch + (size_t)3 * SLOT;
    float*  bx2   = scratch + (size_t)4 * SLOT;
    __half* bffn  = (__half*)(scratch + (size_t)5 * SLOT);
    float*  wbase = scratch + WBASE;
    __half* twq_s = (__half*)(wbase + 0 * (size_t)WSZ);
    __half* twk_s = (__half*)(wbase + 1 * (size_t)WSZ);
    __half* twv_s = (__half*)(wbase + 2 * (size_t)WSZ);
    __half* two_s = (__half*)(wbase + 3 * (size_t)WSZ);
    __half* twq_c = (__half*)(wbase + 4 * (size_t)WSZ);
    __half* twk_c = (__half*)(wbase + 5 * (size_t)WSZ);
    __half* twv_c = (__half*)(wbase + 6 * (size_t)WSZ);
    __half* two_c = (__half*)(wbase + 7 * (size_t)WSZ);
    __half* tw1   = (__half*)(wbase + 8 * (size_t)WSZ);    // [F][D] half
    __half* tw2   = (__half*)(wbase + 12 * (size_t)WSZ);   // [D][F] half
    __half* hmem  = (__half*)(wbase + 16 * (size_t)WSZ);   // [B*LS, D] half

    float* out   = (float*)d_out;
    float* o_mlp = out;
    float* o_ks  = out + (size_t)1 * SLOT;
    float* o_vs  = out + (size_t)2 * SLOT;
    float* o_kc  = out + (size_t)3 * SLOT;
    float* o_vc  = out + (size_t)4 * SLOT;

    cudaFuncSetAttribute(tc_gemm<1>, cudaFuncAttributeMaxDynamicSharedMemorySize, TC_SMEM_BYTES);
    cudaFuncSetAttribute(tc_gemm<2>, cudaFuncAttributeMaxDynamicSharedMemorySize, TC_SMEM_BYTES);
    cudaFuncSetAttribute(tc_gemm<3>, cudaFuncAttributeMaxDynamicSharedMemorySize, TC_SMEM_BYTES);
    cudaFuncSetAttribute(tc_gemm<4>, cudaFuncAttributeMaxDynamicSharedMemorySize, TC_SMEM_BYTES);
    cudaFuncSetAttribute(attn_tc<0>, cudaFuncAttributeMaxDynamicSharedMemorySize, ATT_SMEM0);
    cudaFuncSetAttribute(attn_tc<1>, cudaFuncAttributeMaxDynamicSharedMemorySize, ATT_SMEM1);

    // ---- preprocess: transpose+fp16 weights, fp16 memory ----
    const dim3 xb(32, 8);
    xpose_f16<<<dim3(DD/32, DD/32), xb>>>(wq_s, twq_s, DD, DD);
    xpose_f16<<<dim3(DD/32, DD/32), xb>>>(wk_s, twk_s, DD, DD);
    xpose_f16<<<dim3(DD/32, DD/32), xb>>>(wv_s, twv_s, DD, DD);
    xpose_f16<<<dim3(DD/32, DD/32), xb>>>(wo_s, two_s, DD, DD);
    xpose_f16<<<dim3(DD/32, DD/32), xb>>>(wq_c, twq_c, DD, DD);
    xpose_f16<<<dim3(DD/32, DD/32), xb>>>(wk_c, twk_c, DD, DD);
    xpose_f16<<<dim3(DD/32, DD/32), xb>>>(wv_c, twv_c, DD, DD);
    xpose_f16<<<dim3(DD/32, DD/32), xb>>>(wo_c, two_c, DD, DD);
    xpose_f16<<<dim3(FF/32, DD/32), xb>>>(w1, tw1, DD, FF);
    xpose_f16<<<dim3(DD/32, FF/32), xb>>>(w2, tw2, FF, DD);
    f32_to_f16<<<(4*WSZ)/4/256, 256>>>((const float4*)memory, (__half2*)hmem);

    const dim3 gD(DD / 128, MTOT / 128);   // (8, 32)
    const dim3 gF(FF / 128, MTOT / 128);   // (32, 32)
    const dim3 gA(LT / 64, HH, BB);

    // ---- self-attention block ----
    rmsnorm_kernel<<<MTOT, 256>>>(x, gamma_sa, (__half2*)bh);
    tc_gemm<4><<<gD, 256, TC_SMEM_BYTES>>>(bh, twq_s, bq,   nullptr, MTOT, DD, DD);
    tc_gemm<1><<<gD, 256, TC_SMEM_BYTES>>>(bh, twk_s, o_ks, nullptr, MTOT, DD, DD);
    tc_gemm<1><<<gD, 256, TC_SMEM_BYTES>>>(bh, twv_s, o_vs, nullptr, MTOT, DD, DD);
    attn_tc<0><<<gA, 128, ATT_SMEM0>>>(bq, o_ks, o_vs, nullptr, battn);
    tc_gemm<2><<<gD, 256, TC_SMEM_BYTES>>>(battn, two_s, bx1, x, MTOT, DD, DD);

    // ---- cross-attention block ----
    rmsnorm_kernel<<<MTOT, 256>>>(bx1, gamma_ca, (__half2*)bh);
    tc_gemm<4><<<gD, 256, TC_SMEM_BYTES>>>(bh,   twq_c, bq,   nullptr, MTOT, DD, DD);
    tc_gemm<1><<<gD, 256, TC_SMEM_BYTES>>>(hmem, twk_c, o_kc, nullptr, MTOT, DD, DD);
    tc_gemm<1><<<gD, 256, TC_SMEM_BYTES>>>(hmem, twv_c, o_vc, nullptr, MTOT, DD, DD);
    attn_tc<1><<<gA, 128, ATT_SMEM1>>>(bq, o_kc, o_vc, pos_emb, battn);
    tc_gemm<2><<<gD, 256, TC_SMEM_BYTES>>>(battn, two_c, bx2, bx1, MTOT, DD, DD);

    // ---- FFN block ----
    rmsnorm_kernel<<<MTOT, 256>>>(bx2, gamma_m, (__half2*)bh);
    tc_gemm<3><<<gF, 256, TC_SMEM_BYTES>>>(bh,   tw1, (float*)bffn, nullptr, MTOT, FF, DD);
    tc_gemm<2><<<gD, 256, TC_SMEM_BYTES>>>(bffn, tw2, o_mlp, bx2,   MTOT, DD, FF);
}

// round 12
// speedup vs baseline: 1.6797x; 1.1712x over previous
#include <cuda_runtime.h>
#include <cuda_fp16.h>
#include <cstdint>

// Problem constants
#define BB 4
#define LT 1024
#define LS 1024
#define DD 1024
#define HH 16
#define HD 64
#define FF 4096
#define MTOT (BB*LT)   // 4096 rows

#define SLOT (MTOT*DD)                     // 4M floats
#define WSZ  (DD*DD)                       // 1M floats
// scratch float-slot layout:
//   [0..5)*SLOT : bh(half), bq(half), battn(half), bx1(f32), bx2(f32)
//   5*SLOT      : bffn (half, MTOT*FF)
//   WBASE       : half weightsT + half memory (20 WSZ floats)
//   HKV_BASE    : 4 half KV buffers (8M floats)
//   HB_BASE     : half pos_emb (8M floats)
#define WBASE    ((size_t)5*SLOT + (size_t)MTOT*FF)
#define HKV_BASE (WBASE + 20*(size_t)WSZ)
#define HB_BASE  (HKV_BASE + 8*(size_t)WSZ)
__device__ float g_scratch[HB_BASE + 8*(size_t)WSZ];

// ---------------------------------------------------------------------------
__device__ __forceinline__ void mma_f16(float* d, const uint32_t* a, const uint32_t* b) {
    asm volatile(
        "mma.sync.aligned.m16n8k16.row.col.f32.f16.f16.f32 "
        "{%0,%1,%2,%3}, {%4,%5,%6,%7}, {%8,%9}, {%0,%1,%2,%3};"
        : "+f"(d[0]), "+f"(d[1]), "+f"(d[2]), "+f"(d[3])
        : "r"(a[0]), "r"(a[1]), "r"(a[2]), "r"(a[3]), "r"(b[0]), "r"(b[1]));
}

__device__ __forceinline__ void cp16(uint32_t dst, const void* src) {
    asm volatile("cp.async.cg.shared.global [%0], [%1], 16;" :: "r"(dst), "l"(src));
}

__device__ __forceinline__ uint32_t pack_h2(__half lo, __half hi) {
    __half2 h = __halves2half2(lo, hi);
    return *(uint32_t*)&h;
}

// ---------------------------------------------------------------------------
// Preprocess: fp32 -> fp16 elementwise
__global__ void f32_to_f16(const float4* __restrict__ in, __half2* __restrict__ out)
{
    int idx = blockIdx.x * 256 + threadIdx.x;
    float4 v = in[idx];
    out[idx * 2]     = __floats2half2_rn(v.x, v.y);
    out[idx * 2 + 1] = __floats2half2_rn(v.z, v.w);
}

// Preprocess: transpose + fp16: in[K][N] f32 -> out[N][K] half
__global__ void xpose_f16(const float* __restrict__ in, __half* __restrict__ out,
                          int K, int N)
{
    __shared__ float t[32][33];
    int n0 = blockIdx.x * 32, k0 = blockIdx.y * 32;
    int tx = threadIdx.x, ty = threadIdx.y;   // 32 x 8
    #pragma unroll
    for (int i = 0; i < 4; i++)
        t[ty + i * 8][tx] = in[(size_t)(k0 + ty + i * 8) * N + n0 + tx];
    __syncthreads();
    #pragma unroll
    for (int i = 0; i < 4; i++)
        out[(size_t)(n0 + ty + i * 8) * K + k0 + tx] = __float2half_rn(t[tx][ty + i * 8]);
}

// ---------------------------------------------------------------------------
// RMSNorm: fp32 in -> fp16 out
__global__ void rmsnorm_kernel(const float* __restrict__ x,
                               const float* __restrict__ g,
                               __half2* __restrict__ out)
{
    __shared__ float red[256];
    int row = blockIdx.x;
    int tid = threadIdx.x;
    const float4* xr = (const float4*)(x + (size_t)row * DD);
    float4 v = xr[tid];
    float ss = v.x*v.x + v.y*v.y + v.z*v.z + v.w*v.w;
    red[tid] = ss;
    __syncthreads();
    #pragma unroll
    for (int s = 128; s > 0; s >>= 1) {
        if (tid < s) red[tid] += red[tid + s];
        __syncthreads();
    }
    float inv = rsqrtf(red[0] * (1.0f/(float)DD) + 1e-6f);
    const float4 gg = ((const float4*)g)[tid];
    __half2* op = out + (size_t)row * (DD/2);
    op[tid * 2]     = __floats2half2_rn(v.x * inv * gg.x, v.y * inv * gg.y);
    op[tid * 2 + 1] = __floats2half2_rn(v.z * inv * gg.z, v.w * inv * gg.w);
}

// ---------------------------------------------------------------------------
// FP16 tensor-core GEMM (R11-proven mainloop).
// Epilogues: 1 KV f32 + half copy, 2 resid f32, 3 relu->half, 4 plain->half.
#define TC_BK 32                             // halves per stage
#define AW 20                                // row stride in words (16+4 pad)
#define TILE_W (128 * AW)
#define STAGE_W (2 * TILE_W)
#define TC_SMEM_BYTES (4 * STAGE_W * 4)

template<int EPI>
__global__ __launch_bounds__(256)
void tc_gemm(const __half* __restrict__ A, const __half* __restrict__ BT,
             float* __restrict__ C, const float* __restrict__ R,
             __half* __restrict__ Hout,
             int M, int N, int K)
{
    extern __shared__ float sm[];
    const uint32_t smb = (uint32_t)__cvta_generic_to_shared(sm);

    const int tid  = threadIdx.x;
    const int wid  = tid >> 5;
    const int lane = tid & 31;
    const int g    = lane >> 2;
    const int t    = lane & 3;
    const int wm   = wid & 1;
    const int wn   = wid >> 1;
    const int m0   = blockIdx.y * 128;
    const int n0   = blockIdx.x * 128;

    const __half* Ag = A  + (size_t)m0 * K;
    const __half* Bg = BT + (size_t)n0 * K;

    float acc[4][4][4];
    #pragma unroll
    for (int mi = 0; mi < 4; mi++)
        #pragma unroll
        for (int ni = 0; ni < 4; ni++)
            #pragma unroll
            for (int r = 0; r < 4; r++) acc[mi][ni][r] = 0.0f;

    const int NT = K / TC_BK;

    #define G_LOAD(s, k0)                                                     \
    {                                                                         \
        uint32_t ab_ = smb + (uint32_t)((s) * STAGE_W * 4);                   \
        uint32_t bb_ = ab_ + (uint32_t)(TILE_W * 4);                          \
        _Pragma("unroll")                                                     \
        for (int i_ = 0; i_ < 2; i_++) {                                      \
            int idx_ = tid + i_ * 256;                                        \
            int r_ = idx_ >> 2, c_ = idx_ & 3;                                \
            cp16(ab_ + (uint32_t)((r_ * AW + c_ * 4) << 2),                   \
                 Ag + (size_t)r_ * K + (k0) + c_ * 8);                        \
            cp16(bb_ + (uint32_t)((r_ * AW + c_ * 4) << 2),                   \
                 Bg + (size_t)r_ * K + (k0) + c_ * 8);                        \
        }                                                                     \
    }

    G_LOAD(0, 0);
    asm volatile("cp.async.commit_group;");
    G_LOAD(1, TC_BK);
    asm volatile("cp.async.commit_group;");

    for (int kt = 0; kt < NT; kt++) {
        if (kt + 2 < NT) {
            G_LOAD((kt + 2) & 3, (kt + 2) * TC_BK);
        }
        asm volatile("cp.async.commit_group;");
        asm volatile("cp.async.wait_group 2;");
        __syncthreads();

        const uint32_t* As = (const uint32_t*)sm + (kt & 3) * STAGE_W;
        const uint32_t* Bs = As + TILE_W;
        const uint32_t* Ab = As + (wm * 64 + g) * AW + t;
        const uint32_t* Bb = Bs + (wn * 32 + g) * AW + t;

        #pragma unroll
        for (int kk = 0; kk < 2; kk++) {
            uint32_t af[4][4];
            uint32_t bf[4][2];
            #pragma unroll
            for (int mi = 0; mi < 4; mi++) {
                const uint32_t* p = Ab + mi * 16 * AW + kk * 8;
                af[mi][0] = p[0];
                af[mi][1] = p[8 * AW];
                af[mi][2] = p[4];
                af[mi][3] = p[8 * AW + 4];
            }
            #pragma unroll
            for (int ni = 0; ni < 4; ni++) {
                const uint32_t* p = Bb + ni * 8 * AW + kk * 8;
                bf[ni][0] = p[0];
                bf[ni][1] = p[4];
            }
            #pragma unroll
            for (int mi = 0; mi < 4; mi++)
                #pragma unroll
                for (int ni = 0; ni < 4; ni++)
                    mma_f16(acc[mi][ni], af[mi], bf[ni]);
        }
    }
    #undef G_LOAD

    const int mbase = m0 + wm * 64 + g;
    const int nbase = n0 + wn * 32 + 2 * t;

    if (EPI == 1) {
        #pragma unroll
        for (int mi = 0; mi < 4; mi++) {
            #pragma unroll
            for (int ni = 0; ni < 4; ni++) {
                #pragma unroll
                for (int hf = 0; hf < 2; hf++) {
                    int m = mbase + mi * 16 + hf * 8;
                    int b = m >> 10, l = m & 1023;
                    int n = nbase + ni * 8;
                    int h = n >> 6, d = n & 63;
                    size_t idx = (((size_t)(b * HH + h) * LT + l) << 6) + d;
                    float v0 = acc[mi][ni][hf * 2], v1 = acc[mi][ni][hf * 2 + 1];
                    C[idx]     = v0;
                    C[idx + 1] = v1;
                    *(__half2*)&Hout[idx] = __floats2half2_rn(v0, v1);
                }
            }
        }
    } else if (EPI == 3 || EPI == 4) {
        #pragma unroll
        for (int mi = 0; mi < 4; mi++) {
            #pragma unroll
            for (int ni = 0; ni < 4; ni++) {
                int n = nbase + ni * 8;
                #pragma unroll
                for (int hf = 0; hf < 2; hf++) {
                    int m = mbase + mi * 16 + hf * 8;
                    size_t off = (size_t)m * N + n;
                    float v0 = acc[mi][ni][hf * 2], v1 = acc[mi][ni][hf * 2 + 1];
                    if (EPI == 3) { v0 = fmaxf(v0, 0.f); v1 = fmaxf(v1, 0.f); }
                    *(__half2*)&Hout[off] = __floats2half2_rn(v0, v1);
                }
            }
        }
    } else {
        #pragma unroll
        for (int mi = 0; mi < 4; mi++) {
            #pragma unroll
            for (int ni = 0; ni < 4; ni++) {
                int n = nbase + ni * 8;
                #pragma unroll
                for (int hf = 0; hf < 2; hf++) {
                    int m = mbase + mi * 16 + hf * 8;
                    size_t off = (size_t)m * N + n;
                    float2 v = make_float2(acc[mi][ni][hf * 2], acc[mi][ni][hf * 2 + 1]);
                    float2 r = *(const float2*)(R + off);
                    v.x += r.x; v.y += r.y;
                    *(float2*)(C + off) = v;
                }
            }
        }
    }
}

// ---------------------------------------------------------------------------
// FP16 tensor-core flash attention (m16n8k16, online softmax).
// Q/K/V/bias all half. Smem half offsets (stride 72 halves = 36 words):
//   Qs @0 (64x72), Ks0 @4608, Ks1 @9216, Vs0 @13824, Vs1 @18432,
//   Ps @23040, Bi0 @27648, Bi1 @32256
#define ATT_SMEM0 (27648 * 2)
#define ATT_SMEM1 (36864 * 2)

// half tile loader: 64 rows x 64 halves (128B/row), 512 chunks, 4/thread
#define LOAD_TILE_H(dstoff, srcptr, srcstride)                                \
    _Pragma("unroll")                                                         \
    for (int i_ = 0; i_ < 4; i_++) {                                          \
        int idx_ = tid + i_ * 128;                                            \
        int r_ = idx_ >> 3, c_ = (idx_ & 7) * 8;                              \
        cp16(sbase + (uint32_t)(((dstoff) + r_ * 72 + c_) * 2),               \
             (srcptr) + (size_t)r_ * (srcstride) + c_);                       \
    }

template<int MODE>
__global__ __launch_bounds__(128)
void attn_tc(const __half* __restrict__ Q, const __half* __restrict__ K,
             const __half* __restrict__ V, const __half* __restrict__ bias,
             __half* __restrict__ O)
{
    extern __shared__ __half smh[];
    const int tid  = threadIdx.x;
    const int wid  = tid >> 5;
    const int lane = tid & 31;
    const int g    = lane >> 2;
    const int t    = lane & 3;
    const int qt   = blockIdx.x;
    const int h    = blockIdx.y;
    const int b    = blockIdx.z;

    const uint32_t sbase = (uint32_t)__cvta_generic_to_shared(smh);

    const __half* Qg = Q + ((size_t)(b * LT) + qt * 64) * DD + h * HD;
    const __half* Kg = K + ((size_t)(b * HH + h)) * LS * HD;
    const __half* Vg = V + ((size_t)(b * HH + h)) * LS * HD;
    const __half* Bg = (MODE == 1) ? bias + ((size_t)h * LT + qt * 64) * LS : nullptr;

    {
        LOAD_TILE_H(0,     Qg, DD);
        LOAD_TILE_H(4608,  Kg, HD);
        LOAD_TILE_H(13824, Vg, HD);
        if (MODE == 1) {
            LOAD_TILE_H(27648, Bg, LS);
        }
        asm volatile("cp.async.commit_group;");
    }

    float oacc[8][4];
    #pragma unroll
    for (int ni = 0; ni < 8; ni++)
        #pragma unroll
        for (int r = 0; r < 4; r++) oacc[ni][r] = 0.0f;

    float mrow[2] = { -1e30f, -1e30f };
    float lrow[2] = { 0.0f, 0.0f };

    const int ktmax = (MODE == 0) ? qt : (LS / 64 - 1);

    for (int kt = 0; kt <= ktmax; kt++) {
        const int cur = kt & 1;
        __syncthreads();
        if (kt + 1 <= ktmax) {
            const int nk = kt + 1;
            const int koff = cur ? 4608 : 9216;
            const int voff = cur ? 13824 : 18432;
            const __half* kp = Kg + (size_t)nk * 64 * HD;
            const __half* vp = Vg + (size_t)nk * 64 * HD;
            LOAD_TILE_H(koff, kp, HD);
            LOAD_TILE_H(voff, vp, HD);
            if (MODE == 1) {
                const int boff = cur ? 27648 : 32256;
                const __half* bp = Bg + (size_t)nk * 64;
                LOAD_TILE_H(boff, bp, LS);
            }
            asm volatile("cp.async.commit_group;");
            asm volatile("cp.async.wait_group 1;");
        } else {
            asm volatile("cp.async.wait_group 0;");
        }
        __syncthreads();

        const int koff = cur ? 9216 : 4608;
        const int voff = cur ? 18432 : 13824;
        const int boff = cur ? 32256 : 27648;

        // ---- S = Q K^T  (fp16 m16n8k16) ----
        float sacc[8][4];
        #pragma unroll
        for (int ni = 0; ni < 8; ni++)
            #pragma unroll
            for (int r = 0; r < 4; r++) sacc[ni][r] = 0.0f;

        {
            const uint32_t* qb = (const uint32_t*)smh + (wid * 16 + g) * 36 + t;
            const uint32_t* kb = (const uint32_t*)(smh + koff) + g * 36 + t;
            #pragma unroll
            for (int kk = 0; kk < 4; kk++) {
                uint32_t a[4];
                a[0] = qb[kk * 8];
                a[1] = qb[288 + kk * 8];
                a[2] = qb[kk * 8 + 4];
                a[3] = qb[288 + kk * 8 + 4];
                #pragma unroll
                for (int ni = 0; ni < 8; ni++) {
                    uint32_t bf[2];
                    bf[0] = kb[ni * 288 + kk * 8];
                    bf[1] = kb[ni * 288 + kk * 8 + 4];
                    mma_f16(sacc[ni], a, bf);
                }
            }
        }

        // ---- softmax ----
        #pragma unroll
        for (int hf = 0; hf < 2; hf++) {
            const int row_l = wid * 16 + g + hf * 8;
            float mx = -1e30f;
            #pragma unroll
            for (int ni = 0; ni < 8; ni++) {
                #pragma unroll
                for (int c = 0; c < 2; c++) {
                    float v = sacc[ni][hf * 2 + c] * 0.125f;
                    if (MODE == 0) {
                        if (kt == qt) {
                            int keyl = ni * 8 + 2 * t + c;
                            if (keyl > row_l) v = -1e30f;
                        }
                    } else {
                        v += __half2float(smh[boff + row_l * 72 + ni * 8 + 2 * t + c]);
                    }
                    sacc[ni][hf * 2 + c] = v;
                    mx = fmaxf(mx, v);
                }
            }
            mx = fmaxf(mx, __shfl_xor_sync(0xffffffffu, mx, 1));
            mx = fmaxf(mx, __shfl_xor_sync(0xffffffffu, mx, 2));
            float mnew = fmaxf(mrow[hf], mx);
            float corr = __expf(mrow[hf] - mnew);
            mrow[hf] = mnew;
            float sum = 0.0f;
            #pragma unroll
            for (int ni = 0; ni < 8; ni++) {
                float p0 = __expf(sacc[ni][hf * 2]     - mnew);
                float p1 = __expf(sacc[ni][hf * 2 + 1] - mnew);
                sum += p0 + p1;
                sacc[ni][hf * 2]     = p0;
                sacc[ni][hf * 2 + 1] = p1;
            }
            sum += __shfl_xor_sync(0xffffffffu, sum, 1);
            sum += __shfl_xor_sync(0xffffffffu, sum, 2);
            lrow[hf] = lrow[hf] * corr + sum;
            #pragma unroll
            for (int ni = 0; ni < 8; ni++) {
                oacc[ni][hf * 2]     *= corr;
                oacc[ni][hf * 2 + 1] *= corr;
                *(__half2*)&smh[23040 + row_l * 72 + ni * 8 + 2 * t] =
                    __floats2half2_rn(sacc[ni][hf * 2], sacc[ni][hf * 2 + 1]);
            }
        }
        __syncwarp();

        // ---- O += P V  (fp16 m16n8k16) ----
        {
            const uint32_t* pb = (const uint32_t*)(smh + 23040) + (wid * 16 + g) * 36 + t;
            const __half* vb = smh + voff + (2 * t) * 72 + g;
            #pragma unroll
            for (int kk = 0; kk < 4; kk++) {
                uint32_t a[4];
                a[0] = pb[kk * 8];
                a[1] = pb[288 + kk * 8];
                a[2] = pb[kk * 8 + 4];
                a[3] = pb[288 + kk * 8 + 4];
                const __half* vk = vb + kk * 1152;
                #pragma unroll
                for (int ni = 0; ni < 8; ni++) {
                    uint32_t bf[2];
                    bf[0] = pack_h2(vk[ni * 8],       vk[72 + ni * 8]);
                    bf[1] = pack_h2(vk[576 + ni * 8], vk[648 + ni * 8]);
                    mma_f16(oacc[ni], a, bf);
                }
            }
        }
        __syncwarp();
    }

    // ---- normalize + write O as fp16 ----
    #pragma unroll
    for (int hf = 0; hf < 2; hf++) {
        const int row_l = wid * 16 + g + hf * 8;
        const int qg = qt * 64 + row_l;
        const float invl = 1.0f / lrow[hf];
        __half* op = O + ((size_t)(b * LT) + qg) * DD + h * HD;
        #pragma unroll
        for (int ni = 0; ni < 8; ni++) {
            *(__half2*)(op + ni * 8 + 2 * t) =
                __floats2half2_rn(oacc[ni][hf * 2] * invl, oacc[ni][hf * 2 + 1] * invl);
        }
    }
}

// ---------------------------------------------------------------------------
extern "C" void kernel_launch(void* const* d_in, const int* in_sizes, int n_in,
                              void* d_out, int out_size)
{
    const float* x        = (const float*)d_in[0];
    const float* memory   = (const float*)d_in[1];
    const float* pos_emb  = (const float*)d_in[2];
    const float* gamma_sa = (const float*)d_in[4];
    const float* wq_s     = (const float*)d_in[5];
    const float* wk_s     = (const float*)d_in[6];
    const float* wv_s     = (const float*)d_in[7];
    const float* wo_s     = (const float*)d_in[8];
    const float* gamma_ca = (const float*)d_in[9];
    const float* wq_c     = (const float*)d_in[10];
    const float* wk_c     = (const float*)d_in[11];
    const float* wv_c     = (const float*)d_in[12];
    const float* wo_c     = (const float*)d_in[13];
    const float* gamma_m  = (const float*)d_in[14];
    const float* w1       = (const float*)d_in[15];
    const float* w2       = (const float*)d_in[16];

    float* scratch = nullptr;
    cudaGetSymbolAddress((void**)&scratch, g_scratch);
    __half* bh    = (__half*)(scratch);
    __half* bq    = (__half*)(scratch + (size_t)1 * SLOT);
    __half* battn = (__half*)(scratch + (size_t)2 * SLOT);
    float*  bx1   = scratch + (size_t)3 * SLOT;
    float*  bx2   = scratch + (size_t)4 * SLOT;
    __half* bffn  = (__half*)(scratch + (size_t)5 * SLOT);
    float*  wbase = scratch + WBASE;
    __half* twq_s = (__half*)(wbase + 0 * (size_t)WSZ);
    __half* twk_s = (__half*)(wbase + 1 * (size_t)WSZ);
    __half* twv_s = (__half*)(wbase + 2 * (size_t)WSZ);
    __half* two_s = (__half*)(wbase + 3 * (size_t)WSZ);
    __half* twq_c = (__half*)(wbase + 4 * (size_t)WSZ);
    __half* twk_c = (__half*)(wbase + 5 * (size_t)WSZ);
    __half* twv_c = (__half*)(wbase + 6 * (size_t)WSZ);
    __half* two_c = (__half*)(wbase + 7 * (size_t)WSZ);
    __half* tw1   = (__half*)(wbase + 8 * (size_t)WSZ);
    __half* tw2   = (__half*)(wbase + 12 * (size_t)WSZ);
    __half* hmem  = (__half*)(wbase + 16 * (size_t)WSZ);
    float*  hkvb  = scratch + HKV_BASE;
    __half* hks   = (__half*)(hkvb + 0 * (size_t)(SLOT/2));
    __half* hvs   = (__half*)(hkvb + 1 * (size_t)(SLOT/2));
    __half* hkc   = (__half*)(hkvb + 2 * (size_t)(SLOT/2));
    __half* hvc   = (__half*)(hkvb + 3 * (size_t)(SLOT/2));
    __half* hbias = (__half*)(scratch + HB_BASE);

    float* out   = (float*)d_out;
    float* o_mlp = out;
    float* o_ks  = out + (size_t)1 * SLOT;
    float* o_vs  = out + (size_t)2 * SLOT;
    float* o_kc  = out + (size_t)3 * SLOT;
    float* o_vc  = out + (size_t)4 * SLOT;

    cudaFuncSetAttribute(tc_gemm<1>, cudaFuncAttributeMaxDynamicSharedMemorySize, TC_SMEM_BYTES);
    cudaFuncSetAttribute(tc_gemm<2>, cudaFuncAttributeMaxDynamicSharedMemorySize, TC_SMEM_BYTES);
    cudaFuncSetAttribute(tc_gemm<3>, cudaFuncAttributeMaxDynamicSharedMemorySize, TC_SMEM_BYTES);
    cudaFuncSetAttribute(tc_gemm<4>, cudaFuncAttributeMaxDynamicSharedMemorySize, TC_SMEM_BYTES);
    cudaFuncSetAttribute(attn_tc<0>, cudaFuncAttributeMaxDynamicSharedMemorySize, ATT_SMEM0);
    cudaFuncSetAttribute(attn_tc<1>, cudaFuncAttributeMaxDynamicSharedMemorySize, ATT_SMEM1);

    // ---- preprocess ----
    const dim3 xb(32, 8);
    xpose_f16<<<dim3(DD/32, DD/32), xb>>>(wq_s, twq_s, DD, DD);
    xpose_f16<<<dim3(DD/32, DD/32), xb>>>(wk_s, twk_s, DD, DD);
    xpose_f16<<<dim3(DD/32, DD/32), xb>>>(wv_s, twv_s, DD, DD);
    xpose_f16<<<dim3(DD/32, DD/32), xb>>>(wo_s, two_s, DD, DD);
    xpose_f16<<<dim3(DD/32, DD/32), xb>>>(wq_c, twq_c, DD, DD);
    xpose_f16<<<dim3(DD/32, DD/32), xb>>>(wk_c, twk_c, DD, DD);
    xpose_f16<<<dim3(DD/32, DD/32), xb>>>(wv_c, twv_c, DD, DD);
    xpose_f16<<<dim3(DD/32, DD/32), xb>>>(wo_c, two_c, DD, DD);
    xpose_f16<<<dim3(FF/32, DD/32), xb>>>(w1, tw1, DD, FF);
    xpose_f16<<<dim3(DD/32, FF/32), xb>>>(w2, tw2, FF, DD);
    f32_to_f16<<<(4*WSZ)/4/256, 256>>>((const float4*)memory, (__half2*)hmem);
    f32_to_f16<<<(16*WSZ)/4/256, 256>>>((const float4*)pos_emb, (__half2*)hbias);

    const dim3 gD(DD / 128, MTOT / 128);   // (8, 32)
    const dim3 gF(FF / 128, MTOT / 128);   // (32, 32)
    const dim3 gA(LT / 64, HH, BB);

    // ---- self-attention block ----
    rmsnorm_kernel<<<MTOT, 256>>>(x, gamma_sa, (__half2*)bh);
    tc_gemm<4><<<gD, 256, TC_SMEM_BYTES>>>(bh, twq_s, nullptr, nullptr, bq, MTOT, DD, DD);
    tc_gemm<1><<<gD, 256, TC_SMEM_BYTES>>>(bh, twk_s, o_ks, nullptr, hks, MTOT, DD, DD);
    tc_gemm<1><<<gD, 256, TC_SMEM_BYTES>>>(bh, twv_s, o_vs, nullptr, hvs, MTOT, DD, DD);
    attn_tc<0><<<gA, 128, ATT_SMEM0>>>(bq, hks, hvs, nullptr, battn);
    tc_gemm<2><<<gD, 256, TC_SMEM_BYTES>>>(battn, two_s, bx1, x, nullptr, MTOT, DD, DD);

    // ---- cross-attention block ----
    rmsnorm_kernel<<<MTOT, 256>>>(bx1, gamma_ca, (__half2*)bh);
    tc_gemm<4><<<gD, 256, TC_SMEM_BYTES>>>(bh,   twq_c, nullptr, nullptr, bq, MTOT, DD, DD);
    tc_gemm<1><<<gD, 256, TC_SMEM_BYTES>>>(hmem, twk_c, o_kc, nullptr, hkc, MTOT, DD, DD);
    tc_gemm<1><<<gD, 256, TC_SMEM_BYTES>>>(hmem, twv_c, o_vc, nullptr, hvc, MTOT, DD, DD);
    attn_tc<1><<<gA, 128, ATT_SMEM1>>>(bq, hkc, hvc, hbias, battn);
    tc_gemm<2><<<gD, 256, TC_SMEM_BYTES>>>(battn, two_c, bx2, bx1, nullptr, MTOT, DD, DD);

    // ---- FFN block ----
    rmsnorm_kernel<<<MTOT, 256>>>(bx2, gamma_m, (__half2*)bh);
    tc_gemm<3><<<gF, 256, TC_SMEM_BYTES>>>(bh,   tw1, nullptr, nullptr, bffn, MTOT, FF, DD);
    tc_gemm<2><<<gD, 256, TC_SMEM_BYTES>>>(bffn, tw2, o_mlp, bx2, nullptr, MTOT, DD, FF);
}

// round 13
// speedup vs baseline: 1.7494x; 1.0415x over previous
#include <cuda_runtime.h>
#include <cuda_fp16.h>
#include <cstdint>

// Problem constants
#define BB 4
#define LT 1024
#define LS 1024
#define DD 1024
#define HH 16
#define HD 64
#define FF 4096
#define MTOT (BB*LT)   // 4096 rows

#define SLOT (MTOT*DD)                     // 4M floats
#define WSZ  (DD*DD)                       // 1M floats
#define WBASE    ((size_t)5*SLOT + (size_t)MTOT*FF)
#define HKV_BASE (WBASE + 20*(size_t)WSZ)
#define HB_BASE  (HKV_BASE + 8*(size_t)WSZ)
__device__ float g_scratch[HB_BASE + 8*(size_t)WSZ];

// ---------------------------------------------------------------------------
__device__ __forceinline__ void mma_f16(float* d, const uint32_t* a, const uint32_t* b) {
    asm volatile(
        "mma.sync.aligned.m16n8k16.row.col.f32.f16.f16.f32 "
        "{%0,%1,%2,%3}, {%4,%5,%6,%7}, {%8,%9}, {%0,%1,%2,%3};"
        : "+f"(d[0]), "+f"(d[1]), "+f"(d[2]), "+f"(d[3])
        : "r"(a[0]), "r"(a[1]), "r"(a[2]), "r"(a[3]), "r"(b[0]), "r"(b[1]));
}

__device__ __forceinline__ void cp16(uint32_t dst, const void* src) {
    asm volatile("cp.async.cg.shared.global [%0], [%1], 16;" :: "r"(dst), "l"(src));
}

__device__ __forceinline__ void ldsm4(uint32_t* r, uint32_t saddr) {
    asm volatile("ldmatrix.sync.aligned.m8n8.x4.shared.b16 {%0,%1,%2,%3}, [%4];"
        : "=r"(r[0]), "=r"(r[1]), "=r"(r[2]), "=r"(r[3]) : "r"(saddr));
}

__device__ __forceinline__ uint32_t pack_h2(__half lo, __half hi) {
    __half2 h = __halves2half2(lo, hi);
    return *(uint32_t*)&h;
}

// ---------------------------------------------------------------------------
// Preprocess: fp32 -> fp16 elementwise
__global__ void f32_to_f16(const float4* __restrict__ in, __half2* __restrict__ out)
{
    int idx = blockIdx.x * 256 + threadIdx.x;
    float4 v = in[idx];
    out[idx * 2]     = __floats2half2_rn(v.x, v.y);
    out[idx * 2 + 1] = __floats2half2_rn(v.z, v.w);
}

// Preprocess: transpose + fp16: in[K][N] f32 -> out[N][K] half
__global__ void xpose_f16(const float* __restrict__ in, __half* __restrict__ out,
                          int K, int N)
{
    __shared__ float t[32][33];
    int n0 = blockIdx.x * 32, k0 = blockIdx.y * 32;
    int tx = threadIdx.x, ty = threadIdx.y;   // 32 x 8
    #pragma unroll
    for (int i = 0; i < 4; i++)
        t[ty + i * 8][tx] = in[(size_t)(k0 + ty + i * 8) * N + n0 + tx];
    __syncthreads();
    #pragma unroll
    for (int i = 0; i < 4; i++)
        out[(size_t)(n0 + ty + i * 8) * K + k0 + tx] = __float2half_rn(t[tx][ty + i * 8]);
}

// Batched 1024x1024 transpose+fp16: blockIdx.z selects source; dst = wbase + z*WSZ floats
struct XP8 { const float* src[8]; };
__global__ void xpose_f16_b8(XP8 p, float* __restrict__ wbase)
{
    __shared__ float t[32][33];
    const float* in = p.src[blockIdx.z];
    __half* out = (__half*)(wbase + (size_t)blockIdx.z * WSZ);
    int n0 = blockIdx.x * 32, k0 = blockIdx.y * 32;
    int tx = threadIdx.x, ty = threadIdx.y;
    #pragma unroll
    for (int i = 0; i < 4; i++)
        t[ty + i * 8][tx] = in[(size_t)(k0 + ty + i * 8) * DD + n0 + tx];
    __syncthreads();
    #pragma unroll
    for (int i = 0; i < 4; i++)
        out[(size_t)(n0 + ty + i * 8) * DD + k0 + tx] = __float2half_rn(t[tx][ty + i * 8]);
}

// ---------------------------------------------------------------------------
// RMSNorm: fp32 in -> fp16 out
__global__ void rmsnorm_kernel(const float* __restrict__ x,
                               const float* __restrict__ g,
                               __half2* __restrict__ out)
{
    __shared__ float red[256];
    int row = blockIdx.x;
    int tid = threadIdx.x;
    const float4* xr = (const float4*)(x + (size_t)row * DD);
    float4 v = xr[tid];
    float ss = v.x*v.x + v.y*v.y + v.z*v.z + v.w*v.w;
    red[tid] = ss;
    __syncthreads();
    #pragma unroll
    for (int s = 128; s > 0; s >>= 1) {
        if (tid < s) red[tid] += red[tid + s];
        __syncthreads();
    }
    float inv = rsqrtf(red[0] * (1.0f/(float)DD) + 1e-6f);
    const float4 gg = ((const float4*)g)[tid];
    __half2* op = out + (size_t)row * (DD/2);
    op[tid * 2]     = __floats2half2_rn(v.x * inv * gg.x, v.y * inv * gg.y);
    op[tid * 2 + 1] = __floats2half2_rn(v.z * inv * gg.z, v.w * inv * gg.w);
}

// ---------------------------------------------------------------------------
// FP16 tensor-core GEMM, ldmatrix fragment loads, 4-stage cp.async pipeline.
// Epilogues: 1 KV f32 + half copy, 2 resid f32, 3 relu->half, 4 plain->half.
#define TC_BK 32                             // halves per stage
#define AW 20                                // row stride in words (16+4 pad)
#define TILE_W (128 * AW)
#define STAGE_W (2 * TILE_W)
#define TC_SMEM_BYTES (4 * STAGE_W * 4)

template<int EPI>
__global__ __launch_bounds__(256)
void tc_gemm(const __half* __restrict__ A, const __half* __restrict__ BT,
             float* __restrict__ C, const float* __restrict__ R,
             __half* __restrict__ Hout,
             int M, int N, int K)
{
    extern __shared__ float sm[];
    const uint32_t smb = (uint32_t)__cvta_generic_to_shared(sm);

    const int tid  = threadIdx.x;
    const int wid  = tid >> 5;
    const int lane = tid & 31;
    const int g    = lane >> 2;
    const int t    = lane & 3;
    const int wm   = wid & 1;
    const int wn   = wid >> 1;
    const int m0   = blockIdx.y * 128;
    const int n0   = blockIdx.x * 128;

    // ldmatrix lane-address patterns (R7-verified)
    const int fr = (lane & 7) + ((lane >> 3) & 1) * 8;   // A rows
    const int fk = ((lane >> 4) & 1) * 4;                // A k-word sel
    const int br = (lane & 7) + ((lane >> 4) & 1) * 8;   // B rows (within ni-pair)
    const int bk = ((lane >> 3) & 1) * 4;                // B k-word sel
    const uint32_t a_off = (uint32_t)(((wm * 64 + fr) * AW + fk) << 2);
    const uint32_t b_off = (uint32_t)(TILE_W << 2)
                         + (uint32_t)(((wn * 32 + br) * AW + bk) << 2);

    const __half* Ag = A  + (size_t)m0 * K;
    const __half* Bg = BT + (size_t)n0 * K;

    float acc[4][4][4];
    #pragma unroll
    for (int mi = 0; mi < 4; mi++)
        #pragma unroll
        for (int ni = 0; ni < 4; ni++)
            #pragma unroll
            for (int r = 0; r < 4; r++) acc[mi][ni][r] = 0.0f;

    const int NT = K / TC_BK;

    #define G_LOAD(s, k0)                                                     \
    {                                                                         \
        uint32_t ab_ = smb + (uint32_t)((s) * STAGE_W * 4);                   \
        uint32_t bb_ = ab_ + (uint32_t)(TILE_W * 4);                          \
        _Pragma("unroll")                                                     \
        for (int i_ = 0; i_ < 2; i_++) {                                      \
            int idx_ = tid + i_ * 256;                                        \
            int r_ = idx_ >> 2, c_ = idx_ & 3;                                \
            cp16(ab_ + (uint32_t)((r_ * AW + c_ * 4) << 2),                   \
                 Ag + (size_t)r_ * K + (k0) + c_ * 8);                        \
            cp16(bb_ + (uint32_t)((r_ * AW + c_ * 4) << 2),                   \
                 Bg + (size_t)r_ * K + (k0) + c_ * 8);                        \
        }                                                                     \
    }

    G_LOAD(0, 0);
    asm volatile("cp.async.commit_group;");
    G_LOAD(1, TC_BK);
    asm volatile("cp.async.commit_group;");

    for (int kt = 0; kt < NT; kt++) {
        if (kt + 2 < NT) {
            G_LOAD((kt + 2) & 3, (kt + 2) * TC_BK);
        }
        asm volatile("cp.async.commit_group;");
        asm volatile("cp.async.wait_group 2;");
        __syncthreads();

        const uint32_t base  = smb + (uint32_t)((kt & 3) * STAGE_W * 4);
        const uint32_t abase = base + a_off;
        const uint32_t bbase = base + b_off;

        #pragma unroll
        for (int kk = 0; kk < 2; kk++) {
            uint32_t af[4][4];
            uint32_t bfr[2][4];
            #pragma unroll
            for (int mi = 0; mi < 4; mi++)
                ldsm4(af[mi], abase + (uint32_t)(((mi * 16 * AW) + kk * 8) << 2));
            #pragma unroll
            for (int p = 0; p < 2; p++)
                ldsm4(bfr[p], bbase + (uint32_t)(((p * 16 * AW) + kk * 8) << 2));
            #pragma unroll
            for (int mi = 0; mi < 4; mi++)
                #pragma unroll
                for (int ni = 0; ni < 4; ni++)
                    mma_f16(acc[mi][ni], af[mi], &bfr[ni >> 1][(ni & 1) * 2]);
        }
    }
    #undef G_LOAD

    const int mbase = m0 + wm * 64 + g;
    const int nbase = n0 + wn * 32 + 2 * t;

    if (EPI == 1) {
        #pragma unroll
        for (int mi = 0; mi < 4; mi++) {
            #pragma unroll
            for (int ni = 0; ni < 4; ni++) {
                #pragma unroll
                for (int hf = 0; hf < 2; hf++) {
                    int m = mbase + mi * 16 + hf * 8;
                    int b = m >> 10, l = m & 1023;
                    int n = nbase + ni * 8;
                    int h = n >> 6, d = n & 63;
                    size_t idx = (((size_t)(b * HH + h) * LT + l) << 6) + d;
                    float v0 = acc[mi][ni][hf * 2], v1 = acc[mi][ni][hf * 2 + 1];
                    C[idx]     = v0;
                    C[idx + 1] = v1;
                    *(__half2*)&Hout[idx] = __floats2half2_rn(v0, v1);
                }
            }
        }
    } else if (EPI == 3 || EPI == 4) {
        #pragma unroll
        for (int mi = 0; mi < 4; mi++) {
            #pragma unroll
            for (int ni = 0; ni < 4; ni++) {
                int n = nbase + ni * 8;
                #pragma unroll
                for (int hf = 0; hf < 2; hf++) {
                    int m = mbase + mi * 16 + hf * 8;
                    size_t off = (size_t)m * N + n;
                    float v0 = acc[mi][ni][hf * 2], v1 = acc[mi][ni][hf * 2 + 1];
                    if (EPI == 3) { v0 = fmaxf(v0, 0.f); v1 = fmaxf(v1, 0.f); }
                    *(__half2*)&Hout[off] = __floats2half2_rn(v0, v1);
                }
            }
        }
    } else {
        #pragma unroll
        for (int mi = 0; mi < 4; mi++) {
            #pragma unroll
            for (int ni = 0; ni < 4; ni++) {
                int n = nbase + ni * 8;
                #pragma unroll
                for (int hf = 0; hf < 2; hf++) {
                    int m = mbase + mi * 16 + hf * 8;
                    size_t off = (size_t)m * N + n;
                    float2 v = make_float2(acc[mi][ni][hf * 2], acc[mi][ni][hf * 2 + 1]);
                    float2 r = *(const float2*)(R + off);
                    v.x += r.x; v.y += r.y;
                    *(float2*)(C + off) = v;
                }
            }
        }
    }
}

// ---------------------------------------------------------------------------
// FP16 tensor-core flash attention (m16n8k16, online softmax) — R12 proven.
#define ATT_SMEM0 (27648 * 2)
#define ATT_SMEM1 (36864 * 2)

#define LOAD_TILE_H(dstoff, srcptr, srcstride)                                \
    _Pragma("unroll")                                                         \
    for (int i_ = 0; i_ < 4; i_++) {                                          \
        int idx_ = tid + i_ * 128;                                            \
        int r_ = idx_ >> 3, c_ = (idx_ & 7) * 8;                              \
        cp16(sbase + (uint32_t)(((dstoff) + r_ * 72 + c_) * 2),               \
             (srcptr) + (size_t)r_ * (srcstride) + c_);                       \
    }

template<int MODE>
__global__ __launch_bounds__(128)
void attn_tc(const __half* __restrict__ Q, const __half* __restrict__ K,
             const __half* __restrict__ V, const __half* __restrict__ bias,
             __half* __restrict__ O)
{
    extern __shared__ __half smh[];
    const int tid  = threadIdx.x;
    const int wid  = tid >> 5;
    const int lane = tid & 31;
    const int g    = lane >> 2;
    const int t    = lane & 3;
    const int qt   = blockIdx.x;
    const int h    = blockIdx.y;
    const int b    = blockIdx.z;

    const uint32_t sbase = (uint32_t)__cvta_generic_to_shared(smh);

    const __half* Qg = Q + ((size_t)(b * LT) + qt * 64) * DD + h * HD;
    const __half* Kg = K + ((size_t)(b * HH + h)) * LS * HD;
    const __half* Vg = V + ((size_t)(b * HH + h)) * LS * HD;
    const __half* Bg = (MODE == 1) ? bias + ((size_t)h * LT + qt * 64) * LS : nullptr;

    {
        LOAD_TILE_H(0,     Qg, DD);
        LOAD_TILE_H(4608,  Kg, HD);
        LOAD_TILE_H(13824, Vg, HD);
        if (MODE == 1) {
            LOAD_TILE_H(27648, Bg, LS);
        }
        asm volatile("cp.async.commit_group;");
    }

    float oacc[8][4];
    #pragma unroll
    for (int ni = 0; ni < 8; ni++)
        #pragma unroll
        for (int r = 0; r < 4; r++) oacc[ni][r] = 0.0f;

    float mrow[2] = { -1e30f, -1e30f };
    float lrow[2] = { 0.0f, 0.0f };

    const int ktmax = (MODE == 0) ? qt : (LS / 64 - 1);

    for (int kt = 0; kt <= ktmax; kt++) {
        const int cur = kt & 1;
        __syncthreads();
        if (kt + 1 <= ktmax) {
            const int nk = kt + 1;
            const int koff = cur ? 4608 : 9216;
            const int voff = cur ? 13824 : 18432;
            const __half* kp = Kg + (size_t)nk * 64 * HD;
            const __half* vp = Vg + (size_t)nk * 64 * HD;
            LOAD_TILE_H(koff, kp, HD);
            LOAD_TILE_H(voff, vp, HD);
            if (MODE == 1) {
                const int boff = cur ? 27648 : 32256;
                const __half* bp = Bg + (size_t)nk * 64;
                LOAD_TILE_H(boff, bp, LS);
            }
            asm volatile("cp.async.commit_group;");
            asm volatile("cp.async.wait_group 1;");
        } else {
            asm volatile("cp.async.wait_group 0;");
        }
        __syncthreads();

        const int koff = cur ? 9216 : 4608;
        const int voff = cur ? 18432 : 13824;
        const int boff = cur ? 32256 : 27648;

        // ---- S = Q K^T ----
        float sacc[8][4];
        #pragma unroll
        for (int ni = 0; ni < 8; ni++)
            #pragma unroll
            for (int r = 0; r < 4; r++) sacc[ni][r] = 0.0f;

        {
            const uint32_t* qb = (const uint32_t*)smh + (wid * 16 + g) * 36 + t;
            const uint32_t* kb = (const uint32_t*)(smh + koff) + g * 36 + t;
            #pragma unroll
            for (int kk = 0; kk < 4; kk++) {
                uint32_t a[4];
                a[0] = qb[kk * 8];
                a[1] = qb[288 + kk * 8];
                a[2] = qb[kk * 8 + 4];
                a[3] = qb[288 + kk * 8 + 4];
                #pragma unroll
                for (int ni = 0; ni < 8; ni++) {
                    uint32_t bf[2];
                    bf[0] = kb[ni * 288 + kk * 8];
                    bf[1] = kb[ni * 288 + kk * 8 + 4];
                    mma_f16(sacc[ni], a, bf);
                }
            }
        }

        // ---- softmax ----
        #pragma unroll
        for (int hf = 0; hf < 2; hf++) {
            const int row_l = wid * 16 + g + hf * 8;
            float mx = -1e30f;
            #pragma unroll
            for (int ni = 0; ni < 8; ni++) {
                #pragma unroll
                for (int c = 0; c < 2; c++) {
                    float v = sacc[ni][hf * 2 + c] * 0.125f;
                    if (MODE == 0) {
                        if (kt == qt) {
                            int keyl = ni * 8 + 2 * t + c;
                            if (keyl > row_l) v = -1e30f;
                        }
                    } else {
                        v += __half2float(smh[boff + row_l * 72 + ni * 8 + 2 * t + c]);
                    }
                    sacc[ni][hf * 2 + c] = v;
                    mx = fmaxf(mx, v);
                }
            }
            mx = fmaxf(mx, __shfl_xor_sync(0xffffffffu, mx, 1));
            mx = fmaxf(mx, __shfl_xor_sync(0xffffffffu, mx, 2));
            float mnew = fmaxf(mrow[hf], mx);
            float corr = __expf(mrow[hf] - mnew);
            mrow[hf] = mnew;
            float sum = 0.0f;
            #pragma unroll
            for (int ni = 0; ni < 8; ni++) {
                float p0 = __expf(sacc[ni][hf * 2]     - mnew);
                float p1 = __expf(sacc[ni][hf * 2 + 1] - mnew);
                sum += p0 + p1;
                sacc[ni][hf * 2]     = p0;
                sacc[ni][hf * 2 + 1] = p1;
            }
            sum += __shfl_xor_sync(0xffffffffu, sum, 1);
            sum += __shfl_xor_sync(0xffffffffu, sum, 2);
            lrow[hf] = lrow[hf] * corr + sum;
            #pragma unroll
            for (int ni = 0; ni < 8; ni++) {
                oacc[ni][hf * 2]     *= corr;
                oacc[ni][hf * 2 + 1] *= corr;
                *(__half2*)&smh[23040 + row_l * 72 + ni * 8 + 2 * t] =
                    __floats2half2_rn(sacc[ni][hf * 2], sacc[ni][hf * 2 + 1]);
            }
        }
        __syncwarp();

        // ---- O += P V ----
        {
            const uint32_t* pb = (const uint32_t*)(smh + 23040) + (wid * 16 + g) * 36 + t;
            const __half* vb = smh + voff + (2 * t) * 72 + g;
            #pragma unroll
            for (int kk = 0; kk < 4; kk++) {
                uint32_t a[4];
                a[0] = pb[kk * 8];
                a[1] = pb[288 + kk * 8];
                a[2] = pb[kk * 8 + 4];
                a[3] = pb[288 + kk * 8 + 4];
                const __half* vk = vb + kk * 1152;
                #pragma unroll
                for (int ni = 0; ni < 8; ni++) {
                    uint32_t bf[2];
                    bf[0] = pack_h2(vk[ni * 8],       vk[72 + ni * 8]);
                    bf[1] = pack_h2(vk[576 + ni * 8], vk[648 + ni * 8]);
                    mma_f16(oacc[ni], a, bf);
                }
            }
        }
        __syncwarp();
    }

    // ---- normalize + write O as fp16 ----
    #pragma unroll
    for (int hf = 0; hf < 2; hf++) {
        const int row_l = wid * 16 + g + hf * 8;
        const int qg = qt * 64 + row_l;
        const float invl = 1.0f / lrow[hf];
        __half* op = O + ((size_t)(b * LT) + qg) * DD + h * HD;
        #pragma unroll
        for (int ni = 0; ni < 8; ni++) {
            *(__half2*)(op + ni * 8 + 2 * t) =
                __floats2half2_rn(oacc[ni][hf * 2] * invl, oacc[ni][hf * 2 + 1] * invl);
        }
    }
}

// ---------------------------------------------------------------------------
extern "C" void kernel_launch(void* const* d_in, const int* in_sizes, int n_in,
                              void* d_out, int out_size)
{
    const float* x        = (const float*)d_in[0];
    const float* memory   = (const float*)d_in[1];
    const float* pos_emb  = (const float*)d_in[2];
    const float* gamma_sa = (const float*)d_in[4];
    const float* wq_s     = (const float*)d_in[5];
    const float* wk_s     = (const float*)d_in[6];
    const float* wv_s     = (const float*)d_in[7];
    const float* wo_s     = (const float*)d_in[8];
    const float* gamma_ca = (const float*)d_in[9];
    const float* wq_c     = (const float*)d_in[10];
    const float* wk_c     = (const float*)d_in[11];
    const float* wv_c     = (const float*)d_in[12];
    const float* wo_c     = (const float*)d_in[13];
    const float* gamma_m  = (const float*)d_in[14];
    const float* w1       = (const float*)d_in[15];
    const float* w2       = (const float*)d_in[16];

    float* scratch = nullptr;
    cudaGetSymbolAddress((void**)&scratch, g_scratch);
    __half* bh    = (__half*)(scratch);
    __half* bq    = (__half*)(scratch + (size_t)1 * SLOT);
    __half* battn = (__half*)(scratch + (size_t)2 * SLOT);
    float*  bx1   = scratch + (size_t)3 * SLOT;
    float*  bx2   = scratch + (size_t)4 * SLOT;
    __half* bffn  = (__half*)(scratch + (size_t)5 * SLOT);
    float*  wbase = scratch + WBASE;
    __half* twq_s = (__half*)(wbase + 0 * (size_t)WSZ);
    __half* twk_s = (__half*)(wbase + 1 * (size_t)WSZ);
    __half* twv_s = (__half*)(wbase + 2 * (size_t)WSZ);
    __half* two_s = (__half*)(wbase + 3 * (size_t)WSZ);
    __half* twq_c = (__half*)(wbase + 4 * (size_t)WSZ);
    __half* twk_c = (__half*)(wbase + 5 * (size_t)WSZ);
    __half* twv_c = (__half*)(wbase + 6 * (size_t)WSZ);
    __half* two_c = (__half*)(wbase + 7 * (size_t)WSZ);
    __half* tw1   = (__half*)(wbase + 8 * (size_t)WSZ);
    __half* tw2   = (__half*)(wbase + 12 * (size_t)WSZ);
    __half* hmem  = (__half*)(wbase + 16 * (size_t)WSZ);
    float*  hkvb  = scratch + HKV_BASE;
    __half* hks   = (__half*)(hkvb + 0 * (size_t)(SLOT/2));
    __half* hvs   = (__half*)(hkvb + 1 * (size_t)(SLOT/2));
    __half* hkc   = (__half*)(hkvb + 2 * (size_t)(SLOT/2));
    __half* hvc   = (__half*)(hkvb + 3 * (size_t)(SLOT/2));
    __half* hbias = (__half*)(scratch + HB_BASE);

    float* out   = (float*)d_out;
    float* o_mlp = out;
    float* o_ks  = out + (size_t)1 * SLOT;
    float* o_vs  = out + (size_t)2 * SLOT;
    float* o_kc  = out + (size_t)3 * SLOT;
    float* o_vc  = out + (size_t)4 * SLOT;

    cudaFuncSetAttribute(tc_gemm<1>, cudaFuncAttributeMaxDynamicSharedMemorySize, TC_SMEM_BYTES);
    cudaFuncSetAttribute(tc_gemm<2>, cudaFuncAttributeMaxDynamicSharedMemorySize, TC_SMEM_BYTES);
    cudaFuncSetAttribute(tc_gemm<3>, cudaFuncAttributeMaxDynamicSharedMemorySize, TC_SMEM_BYTES);
    cudaFuncSetAttribute(tc_gemm<4>, cudaFuncAttributeMaxDynamicSharedMemorySize, TC_SMEM_BYTES);
    cudaFuncSetAttribute(attn_tc<0>, cudaFuncAttributeMaxDynamicSharedMemorySize, ATT_SMEM0);
    cudaFuncSetAttribute(attn_tc<1>, cudaFuncAttributeMaxDynamicSharedMemorySize, ATT_SMEM1);

    // ---- preprocess (batched) ----
    {
        XP8 p;
        p.src[0] = wq_s; p.src[1] = wk_s; p.src[2] = wv_s; p.src[3] = wo_s;
        p.src[4] = wq_c; p.src[5] = wk_c; p.src[6] = wv_c; p.src[7] = wo_c;
        xpose_f16_b8<<<dim3(DD/32, DD/32, 8), dim3(32, 8)>>>(p, wbase);
    }
    const dim3 xb(32, 8);
    xpose_f16<<<dim3(FF/32, DD/32), xb>>>(w1, tw1, DD, FF);
    xpose_f16<<<dim3(DD/32, FF/32), xb>>>(w2, tw2, FF, DD);
    f32_to_f16<<<(4*WSZ)/4/256, 256>>>((const float4*)memory, (__half2*)hmem);
    f32_to_f16<<<(16*WSZ)/4/256, 256>>>((const float4*)pos_emb, (__half2*)hbias);

    const dim3 gD(DD / 128, MTOT / 128);   // (8, 32)
    const dim3 gF(FF / 128, MTOT / 128);   // (32, 32)
    const dim3 gA(LT / 64, HH, BB);

    // ---- self-attention block ----
    rmsnorm_kernel<<<MTOT, 256>>>(x, gamma_sa, (__half2*)bh);
    tc_gemm<4><<<gD, 256, TC_SMEM_BYTES>>>(bh, twq_s, nullptr, nullptr, bq, MTOT, DD, DD);
    tc_gemm<1><<<gD, 256, TC_SMEM_BYTES>>>(bh, twk_s, o_ks, nullptr, hks, MTOT, DD, DD);
    tc_gemm<1><<<gD, 256, TC_SMEM_BYTES>>>(bh, twv_s, o_vs, nullptr, hvs, MTOT, DD, DD);
    attn_tc<0><<<gA, 128, ATT_SMEM0>>>(bq, hks, hvs, nullptr, battn);
    tc_gemm<2><<<gD, 256, TC_SMEM_BYTES>>>(battn, two_s, bx1, x, nullptr, MTOT, DD, DD);

    // ---- cross-attention block ----
    rmsnorm_kernel<<<MTOT, 256>>>(bx1, gamma_ca, (__half2*)bh);
    tc_gemm<4><<<gD, 256, TC_SMEM_BYTES>>>(bh,   twq_c, nullptr, nullptr, bq, MTOT, DD, DD);
    tc_gemm<1><<<gD, 256, TC_SMEM_BYTES>>>(hmem, twk_c, o_kc, nullptr, hkc, MTOT, DD, DD);
    tc_gemm<1><<<gD, 256, TC_SMEM_BYTES>>>(hmem, twv_c, o_vc, nullptr, hvc, MTOT, DD, DD);
    attn_tc<1><<<gA, 128, ATT_SMEM1>>>(bq, hkc, hvc, hbias, battn);
    tc_gemm<2><<<gD, 256, TC_SMEM_BYTES>>>(battn, two_c, bx2, bx1, nullptr, MTOT, DD, DD);

    // ---- FFN block ----
    rmsnorm_kernel<<<MTOT, 256>>>(bx2, gamma_m, (__half2*)bh);
    tc_gemm<3><<<gF, 256, TC_SMEM_BYTES>>>(bh,   tw1, nullptr, nullptr, bffn, MTOT, FF, DD);
    tc_gemm<2><<<gD, 256, TC_SMEM_BYTES>>>(bffn, tw2, o_mlp, bx2, nullptr, MTOT, DD, FF);
}

// round 14
// speedup vs baseline: 1.7757x; 1.0150x over previous
#include <cuda_runtime.h>
#include <cuda_fp16.h>
#include <cstdint>

// Problem constants
#define BB 4
#define LT 1024
#define LS 1024
#define DD 1024
#define HH 16
#define HD 64
#define FF 4096
#define MTOT (BB*LT)   // 4096 rows

#define SLOT (MTOT*DD)                     // 4M floats
#define WSZ  (DD*DD)                       // 1M (floats or halves, per context)
#define WBASE    ((size_t)5*SLOT + (size_t)MTOT*FF)
#define HKV_BASE (WBASE + 20*(size_t)WSZ)
#define HB_BASE  (HKV_BASE + 8*(size_t)WSZ)
__device__ float g_scratch[HB_BASE + 8*(size_t)WSZ];

// ---------------------------------------------------------------------------
__device__ __forceinline__ void mma_f16(float* d, const uint32_t* a, const uint32_t* b) {
    asm volatile(
        "mma.sync.aligned.m16n8k16.row.col.f32.f16.f16.f32 "
        "{%0,%1,%2,%3}, {%4,%5,%6,%7}, {%8,%9}, {%0,%1,%2,%3};"
        : "+f"(d[0]), "+f"(d[1]), "+f"(d[2]), "+f"(d[3])
        : "r"(a[0]), "r"(a[1]), "r"(a[2]), "r"(a[3]), "r"(b[0]), "r"(b[1]));
}

__device__ __forceinline__ void cp16(uint32_t dst, const void* src) {
    asm volatile("cp.async.cg.shared.global [%0], [%1], 16;" :: "r"(dst), "l"(src));
}

__device__ __forceinline__ void ldsm4(uint32_t* r, uint32_t saddr) {
    asm volatile("ldmatrix.sync.aligned.m8n8.x4.shared.b16 {%0,%1,%2,%3}, [%4];"
        : "=r"(r[0]), "=r"(r[1]), "=r"(r[2]), "=r"(r[3]) : "r"(saddr));
}

__device__ __forceinline__ uint32_t pack_h2(__half lo, __half hi) {
    __half2 h = __halves2half2(lo, hi);
    return *(uint32_t*)&h;
}

// ---------------------------------------------------------------------------
// Preprocess: fp32 -> fp16 elementwise
__global__ void f32_to_f16(const float4* __restrict__ in, __half2* __restrict__ out)
{
    int idx = blockIdx.x * 256 + threadIdx.x;
    float4 v = in[idx];
    out[idx * 2]     = __floats2half2_rn(v.x, v.y);
    out[idx * 2 + 1] = __floats2half2_rn(v.z, v.w);
}

// Preprocess: transpose + fp16: in[K][N] f32 -> out[N][K] half
__global__ void xpose_f16(const float* __restrict__ in, __half* __restrict__ out,
                          int K, int N)
{
    __shared__ float t[32][33];
    int n0 = blockIdx.x * 32, k0 = blockIdx.y * 32;
    int tx = threadIdx.x, ty = threadIdx.y;   // 32 x 8
    #pragma unroll
    for (int i = 0; i < 4; i++)
        t[ty + i * 8][tx] = in[(size_t)(k0 + ty + i * 8) * N + n0 + tx];
    __syncthreads();
    #pragma unroll
    for (int i = 0; i < 4; i++)
        out[(size_t)(n0 + ty + i * 8) * K + k0 + tx] = __float2half_rn(t[tx][ty + i * 8]);
}

// Batched 1024x1024 transpose+fp16; outputs are CONTIGUOUS half arrays
// (spacing WSZ halves) so fused QKV GEMMs can index across weights.
struct XP8 { const float* src[8]; };
__global__ void xpose_f16_b8(XP8 p, __half* __restrict__ hwbase)
{
    __shared__ float t[32][33];
    const float* in = p.src[blockIdx.z];
    __half* out = hwbase + (size_t)blockIdx.z * WSZ;
    int n0 = blockIdx.x * 32, k0 = blockIdx.y * 32;
    int tx = threadIdx.x, ty = threadIdx.y;
    #pragma unroll
    for (int i = 0; i < 4; i++)
        t[ty + i * 8][tx] = in[(size_t)(k0 + ty + i * 8) * DD + n0 + tx];
    __syncthreads();
    #pragma unroll
    for (int i = 0; i < 4; i++)
        out[(size_t)(n0 + ty + i * 8) * DD + k0 + tx] = __float2half_rn(t[tx][ty + i * 8]);
}

// ---------------------------------------------------------------------------
// RMSNorm: fp32 in -> fp16 out
__global__ void rmsnorm_kernel(const float* __restrict__ x,
                               const float* __restrict__ g,
                               __half2* __restrict__ out)
{
    __shared__ float red[256];
    int row = blockIdx.x;
    int tid = threadIdx.x;
    const float4* xr = (const float4*)(x + (size_t)row * DD);
    float4 v = xr[tid];
    float ss = v.x*v.x + v.y*v.y + v.z*v.z + v.w*v.w;
    red[tid] = ss;
    __syncthreads();
    #pragma unroll
    for (int s = 128; s > 0; s >>= 1) {
        if (tid < s) red[tid] += red[tid + s];
        __syncthreads();
    }
    float inv = rsqrtf(red[0] * (1.0f/(float)DD) + 1e-6f);
    const float4 gg = ((const float4*)g)[tid];
    __half2* op = out + (size_t)row * (DD/2);
    op[tid * 2]     = __floats2half2_rn(v.x * inv * gg.x, v.y * inv * gg.y);
    op[tid * 2 + 1] = __floats2half2_rn(v.z * inv * gg.z, v.w * inv * gg.w);
}

// ---------------------------------------------------------------------------
// FP16 tensor-core GEMM, ldmatrix fragment loads, 4-stage cp.async pipeline.
// Epilogues:
//   2 resid f32, 3 relu->half, 4 plain->half,
//   5 self-QKV router (sector0->Hq half; sector1/2 -> KV f32+half),
//   6 cross-KV router (sector0/1 -> KV f32+half).
#define TC_BK 32                             // halves per stage
#define AW 20                                // row stride in words (16+4 pad)
#define TILE_W (128 * AW)
#define STAGE_W (2 * TILE_W)
#define TC_SMEM_BYTES (4 * STAGE_W * 4)

template<int EPI>
__global__ __launch_bounds__(256)
void tc_gemm(const __half* __restrict__ A, const __half* __restrict__ BT,
             float* __restrict__ C, const float* __restrict__ R,
             __half* __restrict__ Hout, __half* __restrict__ Hq,
             int M, int N, int K)
{
    extern __shared__ float sm[];
    const uint32_t smb = (uint32_t)__cvta_generic_to_shared(sm);

    const int tid  = threadIdx.x;
    const int wid  = tid >> 5;
    const int lane = tid & 31;
    const int g    = lane >> 2;
    const int t    = lane & 3;
    const int wm   = wid & 1;
    const int wn   = wid >> 1;
    const int m0   = blockIdx.y * 128;
    const int n0   = blockIdx.x * 128;

    // ldmatrix lane-address patterns (verified)
    const int fr = (lane & 7) + ((lane >> 3) & 1) * 8;
    const int fk = ((lane >> 4) & 1) * 4;
    const int br = (lane & 7) + ((lane >> 4) & 1) * 8;
    const int bk = ((lane >> 3) & 1) * 4;
    const uint32_t a_off = (uint32_t)(((wm * 64 + fr) * AW + fk) << 2);
    const uint32_t b_off = (uint32_t)(TILE_W << 2)
                         + (uint32_t)(((wn * 32 + br) * AW + bk) << 2);

    const __half* Ag = A  + (size_t)m0 * K;
    const __half* Bg = BT + (size_t)n0 * K;

    float acc[4][4][4];
    #pragma unroll
    for (int mi = 0; mi < 4; mi++)
        #pragma unroll
        for (int ni = 0; ni < 4; ni++)
            #pragma unroll
            for (int r = 0; r < 4; r++) acc[mi][ni][r] = 0.0f;

    const int NT = K / TC_BK;

    #define G_LOAD(s, k0)                                                     \
    {                                                                         \
        uint32_t ab_ = smb + (uint32_t)((s) * STAGE_W * 4);                   \
        uint32_t bb_ = ab_ + (uint32_t)(TILE_W * 4);                          \
        _Pragma("unroll")                                                     \
        for (int i_ = 0; i_ < 2; i_++) {                                      \
            int idx_ = tid + i_ * 256;                                        \
            int r_ = idx_ >> 2, c_ = idx_ & 3;                                \
            cp16(ab_ + (uint32_t)((r_ * AW + c_ * 4) << 2),                   \
                 Ag + (size_t)r_ * K + (k0) + c_ * 8);                        \
            cp16(bb_ + (uint32_t)((r_ * AW + c_ * 4) << 2),                   \
                 Bg + (size_t)r_ * K + (k0) + c_ * 8);                        \
        }                                                                     \
    }

    G_LOAD(0, 0);
    asm volatile("cp.async.commit_group;");
    G_LOAD(1, TC_BK);
    asm volatile("cp.async.commit_group;");

    for (int kt = 0; kt < NT; kt++) {
        if (kt + 2 < NT) {
            G_LOAD((kt + 2) & 3, (kt + 2) * TC_BK);
        }
        asm volatile("cp.async.commit_group;");
        asm volatile("cp.async.wait_group 2;");
        __syncthreads();

        const uint32_t base  = smb + (uint32_t)((kt & 3) * STAGE_W * 4);
        const uint32_t abase = base + a_off;
        const uint32_t bbase = base + b_off;

        #pragma unroll
        for (int kk = 0; kk < 2; kk++) {
            uint32_t af[4][4];
            uint32_t bfr[2][4];
            #pragma unroll
            for (int mi = 0; mi < 4; mi++)
                ldsm4(af[mi], abase + (uint32_t)(((mi * 16 * AW) + kk * 8) << 2));
            #pragma unroll
            for (int p = 0; p < 2; p++)
                ldsm4(bfr[p], bbase + (uint32_t)(((p * 16 * AW) + kk * 8) << 2));
            #pragma unroll
            for (int mi = 0; mi < 4; mi++)
                #pragma unroll
                for (int ni = 0; ni < 4; ni++)
                    mma_f16(acc[mi][ni], af[mi], &bfr[ni >> 1][(ni & 1) * 2]);
        }
    }
    #undef G_LOAD

    const int mbase = m0 + wm * 64 + g;
    const int nbase = n0 + wn * 32 + 2 * t;

    if (EPI == 5 || EPI == 6) {
        const int sector = n0 >> 10;           // 1024-col group (uniform per CTA)
        if (EPI == 5 && sector == 0) {
            // Q projection -> half, row stride DD
            #pragma unroll
            for (int mi = 0; mi < 4; mi++) {
                #pragma unroll
                for (int ni = 0; ni < 4; ni++) {
                    int n = nbase + ni * 8;
                    #pragma unroll
                    for (int hf = 0; hf < 2; hf++) {
                        int m = mbase + mi * 16 + hf * 8;
                        *(__half2*)&Hq[(size_t)m * DD + n] =
                            __floats2half2_rn(acc[mi][ni][hf * 2], acc[mi][ni][hf * 2 + 1]);
                    }
                }
            }
        } else {
            const int s = (EPI == 5) ? sector - 1 : sector;   // 0=K, 1=V
            float*  Cb = C    + (size_t)s * SLOT;
            __half* Hb = Hout + (size_t)s * SLOT;
            #pragma unroll
            for (int mi = 0; mi < 4; mi++) {
                #pragma unroll
                for (int ni = 0; ni < 4; ni++) {
                    int n = (nbase + ni * 8) & 1023;
                    int h = n >> 6, d = n & 63;
                    #pragma unroll
                    for (int hf = 0; hf < 2; hf++) {
                        int m = mbase + mi * 16 + hf * 8;
                        int b = m >> 10, l = m & 1023;
                        size_t idx = (((size_t)(b * HH + h) * LT + l) << 6) + d;
                        float v0 = acc[mi][ni][hf * 2], v1 = acc[mi][ni][hf * 2 + 1];
                        *(float2*)&Cb[idx]  = make_float2(v0, v1);
                        *(__half2*)&Hb[idx] = __floats2half2_rn(v0, v1);
                    }
                }
            }
        }
    } else if (EPI == 3 || EPI == 4) {
        #pragma unroll
        for (int mi = 0; mi < 4; mi++) {
            #pragma unroll
            for (int ni = 0; ni < 4; ni++) {
                int n = nbase + ni * 8;
                #pragma unroll
                for (int hf = 0; hf < 2; hf++) {
                    int m = mbase + mi * 16 + hf * 8;
                    size_t off = (size_t)m * N + n;
                    float v0 = acc[mi][ni][hf * 2], v1 = acc[mi][ni][hf * 2 + 1];
                    if (EPI == 3) { v0 = fmaxf(v0, 0.f); v1 = fmaxf(v1, 0.f); }
                    *(__half2*)&Hout[off] = __floats2half2_rn(v0, v1);
                }
            }
        }
    } else {   // EPI == 2
        #pragma unroll
        for (int mi = 0; mi < 4; mi++) {
            #pragma unroll
            for (int ni = 0; ni < 4; ni++) {
                int n = nbase + ni * 8;
                #pragma unroll
                for (int hf = 0; hf < 2; hf++) {
                    int m = mbase + mi * 16 + hf * 8;
                    size_t off = (size_t)m * N + n;
                    float2 v = make_float2(acc[mi][ni][hf * 2], acc[mi][ni][hf * 2 + 1]);
                    float2 r = *(const float2*)(R + off);
                    v.x += r.x; v.y += r.y;
                    *(float2*)(C + off) = v;
                }
            }
        }
    }
}

// ---------------------------------------------------------------------------
// FP16 tensor-core flash attention (m16n8k16, online softmax) — R12/13 proven.
#define ATT_SMEM0 (27648 * 2)
#define ATT_SMEM1 (36864 * 2)

#define LOAD_TILE_H(dstoff, srcptr, srcstride)                                \
    _Pragma("unroll")                                                         \
    for (int i_ = 0; i_ < 4; i_++) {                                          \
        int idx_ = tid + i_ * 128;                                            \
        int r_ = idx_ >> 3, c_ = (idx_ & 7) * 8;                              \
        cp16(sbase + (uint32_t)(((dstoff) + r_ * 72 + c_) * 2),               \
             (srcptr) + (size_t)r_ * (srcstride) + c_);                       \
    }

template<int MODE>
__global__ __launch_bounds__(128)
void attn_tc(const __half* __restrict__ Q, const __half* __restrict__ K,
             const __half* __restrict__ V, const __half* __restrict__ bias,
             __half* __restrict__ O)
{
    extern __shared__ __half smh[];
    const int tid  = threadIdx.x;
    const int wid  = tid >> 5;
    const int lane = tid & 31;
    const int g    = lane >> 2;
    const int t    = lane & 3;
    const int qt   = blockIdx.x;
    const int h    = blockIdx.y;
    const int b    = blockIdx.z;

    const uint32_t sbase = (uint32_t)__cvta_generic_to_shared(smh);

    const __half* Qg = Q + ((size_t)(b * LT) + qt * 64) * DD + h * HD;
    const __half* Kg = K + ((size_t)(b * HH + h)) * LS * HD;
    const __half* Vg = V + ((size_t)(b * HH + h)) * LS * HD;
    const __half* Bg = (MODE == 1) ? bias + ((size_t)h * LT + qt * 64) * LS : nullptr;

    {
        LOAD_TILE_H(0,     Qg, DD);
        LOAD_TILE_H(4608,  Kg, HD);
        LOAD_TILE_H(13824, Vg, HD);
        if (MODE == 1) {
            LOAD_TILE_H(27648, Bg, LS);
        }
        asm volatile("cp.async.commit_group;");
    }

    float oacc[8][4];
    #pragma unroll
    for (int ni = 0; ni < 8; ni++)
        #pragma unroll
        for (int r = 0; r < 4; r++) oacc[ni][r] = 0.0f;

    float mrow[2] = { -1e30f, -1e30f };
    float lrow[2] = { 0.0f, 0.0f };

    const int ktmax = (MODE == 0) ? qt : (LS / 64 - 1);

    for (int kt = 0; kt <= ktmax; kt++) {
        const int cur = kt & 1;
        __syncthreads();
        if (kt + 1 <= ktmax) {
            const int nk = kt + 1;
            const int koff = cur ? 4608 : 9216;
            const int voff = cur ? 13824 : 18432;
            const __half* kp = Kg + (size_t)nk * 64 * HD;
            const __half* vp = Vg + (size_t)nk * 64 * HD;
            LOAD_TILE_H(koff, kp, HD);
            LOAD_TILE_H(voff, vp, HD);
            if (MODE == 1) {
                const int boff = cur ? 27648 : 32256;
                const __half* bp = Bg + (size_t)nk * 64;
                LOAD_TILE_H(boff, bp, LS);
            }
            asm volatile("cp.async.commit_group;");
            asm volatile("cp.async.wait_group 1;");
        } else {
            asm volatile("cp.async.wait_group 0;");
        }
        __syncthreads();

        const int koff = cur ? 9216 : 4608;
        const int voff = cur ? 18432 : 13824;
        const int boff = cur ? 32256 : 27648;

        // ---- S = Q K^T ----
        float sacc[8][4];
        #pragma unroll
        for (int ni = 0; ni < 8; ni++)
            #pragma unroll
            for (int r = 0; r < 4; r++) sacc[ni][r] = 0.0f;

        {
            const uint32_t* qb = (const uint32_t*)smh + (wid * 16 + g) * 36 + t;
            const uint32_t* kb = (const uint32_t*)(smh + koff) + g * 36 + t;
            #pragma unroll
            for (int kk = 0; kk < 4; kk++) {
                uint32_t a[4];
                a[0] = qb[kk * 8];
                a[1] = qb[288 + kk * 8];
                a[2] = qb[kk * 8 + 4];
                a[3] = qb[288 + kk * 8 + 4];
                #pragma unroll
                for (int ni = 0; ni < 8; ni++) {
                    uint32_t bf[2];
                    bf[0] = kb[ni * 288 + kk * 8];
                    bf[1] = kb[ni * 288 + kk * 8 + 4];
                    mma_f16(sacc[ni], a, bf);
                }
            }
        }

        // ---- softmax ----
        #pragma unroll
        for (int hf = 0; hf < 2; hf++) {
            const int row_l = wid * 16 + g + hf * 8;
            float mx = -1e30f;
            #pragma unroll
            for (int ni = 0; ni < 8; ni++) {
                #pragma unroll
                for (int c = 0; c < 2; c++) {
                    float v = sacc[ni][hf * 2 + c] * 0.125f;
                    if (MODE == 0) {
                        if (kt == qt) {
                            int keyl = ni * 8 + 2 * t + c;
                            if (keyl > row_l) v = -1e30f;
                        }
                    } else {
                        v += __half2float(smh[boff + row_l * 72 + ni * 8 + 2 * t + c]);
                    }
                    sacc[ni][hf * 2 + c] = v;
                    mx = fmaxf(mx, v);
                }
            }
            mx = fmaxf(mx, __shfl_xor_sync(0xffffffffu, mx, 1));
            mx = fmaxf(mx, __shfl_xor_sync(0xffffffffu, mx, 2));
            float mnew = fmaxf(mrow[hf], mx);
            float corr = __expf(mrow[hf] - mnew);
            mrow[hf] = mnew;
            float sum = 0.0f;
            #pragma unroll
            for (int ni = 0; ni < 8; ni++) {
                float p0 = __expf(sacc[ni][hf * 2]     - mnew);
                float p1 = __expf(sacc[ni][hf * 2 + 1] - mnew);
                sum += p0 + p1;
                sacc[ni][hf * 2]     = p0;
                sacc[ni][hf * 2 + 1] = p1;
            }
            sum += __shfl_xor_sync(0xffffffffu, sum, 1);
            sum += __shfl_xor_sync(0xffffffffu, sum, 2);
            lrow[hf] = lrow[hf] * corr + sum;
            #pragma unroll
            for (int ni = 0; ni < 8; ni++) {
                oacc[ni][hf * 2]     *= corr;
                oacc[ni][hf * 2 + 1] *= corr;
                *(__half2*)&smh[23040 + row_l * 72 + ni * 8 + 2 * t] =
                    __floats2half2_rn(sacc[ni][hf * 2], sacc[ni][hf * 2 + 1]);
            }
        }
        __syncwarp();

        // ---- O += P V ----
        {
            const uint32_t* pb = (const uint32_t*)(smh + 23040) + (wid * 16 + g) * 36 + t;
            const __half* vb = smh + voff + (2 * t) * 72 + g;
            #pragma unroll
            for (int kk = 0; kk < 4; kk++) {
                uint32_t a[4];
                a[0] = pb[kk * 8];
                a[1] = pb[288 + kk * 8];
                a[2] = pb[kk * 8 + 4];
                a[3] = pb[288 + kk * 8 + 4];
                const __half* vk = vb + kk * 1152;
                #pragma unroll
                for (int ni = 0; ni < 8; ni++) {
                    uint32_t bf[2];
                    bf[0] = pack_h2(vk[ni * 8],       vk[72 + ni * 8]);
                    bf[1] = pack_h2(vk[576 + ni * 8], vk[648 + ni * 8]);
                    mma_f16(oacc[ni], a, bf);
                }
            }
        }
        __syncwarp();
    }

    // ---- normalize + write O as fp16 ----
    #pragma unroll
    for (int hf = 0; hf < 2; hf++) {
        const int row_l = wid * 16 + g + hf * 8;
        const int qg = qt * 64 + row_l;
        const float invl = 1.0f / lrow[hf];
        __half* op = O + ((size_t)(b * LT) + qg) * DD + h * HD;
        #pragma unroll
        for (int ni = 0; ni < 8; ni++) {
            *(__half2*)(op + ni * 8 + 2 * t) =
                __floats2half2_rn(oacc[ni][hf * 2] * invl, oacc[ni][hf * 2 + 1] * invl);
        }
    }
}

// ---------------------------------------------------------------------------
extern "C" void kernel_launch(void* const* d_in, const int* in_sizes, int n_in,
                              void* d_out, int out_size)
{
    const float* x        = (const float*)d_in[0];
    const float* memory   = (const float*)d_in[1];
    const float* pos_emb  = (const float*)d_in[2];
    const float* gamma_sa = (const float*)d_in[4];
    const float* wq_s     = (const float*)d_in[5];
    const float* wk_s     = (const float*)d_in[6];
    const float* wv_s     = (const float*)d_in[7];
    const float* wo_s     = (const float*)d_in[8];
    const float* gamma_ca = (const float*)d_in[9];
    const float* wq_c     = (const float*)d_in[10];
    const float* wk_c     = (const float*)d_in[11];
    const float* wv_c     = (const float*)d_in[12];
    const float* wo_c     = (const float*)d_in[13];
    const float* gamma_m  = (const float*)d_in[14];
    const float* w1       = (const float*)d_in[15];
    const float* w2       = (const float*)d_in[16];

    float* scratch = nullptr;
    cudaGetSymbolAddress((void**)&scratch, g_scratch);
    __half* bh    = (__half*)(scratch);
    __half* bq    = (__half*)(scratch + (size_t)1 * SLOT);
    __half* battn = (__half*)(scratch + (size_t)2 * SLOT);
    float*  bx1   = scratch + (size_t)3 * SLOT;
    float*  bx2   = scratch + (size_t)4 * SLOT;
    __half* bffn  = (__half*)(scratch + (size_t)5 * SLOT);

    // weight region: contiguous HALF arrays now (spacing WSZ halves)
    __half* hw    = (__half*)(scratch + WBASE);
    __half* twq_s = hw + 0 * (size_t)WSZ;
    __half* twk_s = hw + 1 * (size_t)WSZ;     // twq_s..twv_s contiguous for fused QKV
    __half* twv_s = hw + 2 * (size_t)WSZ;
    __half* two_s = hw + 3 * (size_t)WSZ;
    __half* twq_c = hw + 4 * (size_t)WSZ;
    __half* twk_c = hw + 5 * (size_t)WSZ;     // twk_c..twv_c contiguous for fused KV
    __half* twv_c = hw + 6 * (size_t)WSZ;
    __half* two_c = hw + 7 * (size_t)WSZ;
    __half* tw1   = hw + 8  * (size_t)WSZ;    // [F][D], 4 WSZ halves
    __half* tw2   = hw + 12 * (size_t)WSZ;    // [D][F], 4 WSZ halves
    __half* hmem  = hw + 16 * (size_t)WSZ;    // [B*LS, D], 4 WSZ halves

    float*  hkvb  = scratch + HKV_BASE;
    __half* hks   = (__half*)(hkvb);          // hks,hvs contiguous (SLOT halves each)
    __half* hkc   = (__half*)(hkvb + 2 * (size_t)(SLOT/2));  // hkc,hvc contiguous
    __half* hbias = (__half*)(scratch + HB_BASE);

    float* out   = (float*)d_out;
    float* o_mlp = out;
    float* o_ks  = out + (size_t)1 * SLOT;    // o_ks,o_vs contiguous
    float* o_kc  = out + (size_t)3 * SLOT;    // o_kc,o_vc contiguous

    cudaFuncSetAttribute(tc_gemm<2>, cudaFuncAttributeMaxDynamicSharedMemorySize, TC_SMEM_BYTES);
    cudaFuncSetAttribute(tc_gemm<3>, cudaFuncAttributeMaxDynamicSharedMemorySize, TC_SMEM_BYTES);
    cudaFuncSetAttribute(tc_gemm<4>, cudaFuncAttributeMaxDynamicSharedMemorySize, TC_SMEM_BYTES);
    cudaFuncSetAttribute(tc_gemm<5>, cudaFuncAttributeMaxDynamicSharedMemorySize, TC_SMEM_BYTES);
    cudaFuncSetAttribute(tc_gemm<6>, cudaFuncAttributeMaxDynamicSharedMemorySize, TC_SMEM_BYTES);
    cudaFuncSetAttribute(attn_tc<0>, cudaFuncAttributeMaxDynamicSharedMemorySize, ATT_SMEM0);
    cudaFuncSetAttribute(attn_tc<1>, cudaFuncAttributeMaxDynamicSharedMemorySize, ATT_SMEM1);

    // ---- preprocess ----
    {
        XP8 p;
        p.src[0] = wq_s; p.src[1] = wk_s; p.src[2] = wv_s; p.src[3] = wo_s;
        p.src[4] = wq_c; p.src[5] = wk_c; p.src[6] = wv_c; p.src[7] = wo_c;
        xpose_f16_b8<<<dim3(DD/32, DD/32, 8), dim3(32, 8)>>>(p, hw);
    }
    const dim3 xb(32, 8);
    xpose_f16<<<dim3(FF/32, DD/32), xb>>>(w1, tw1, DD, FF);
    xpose_f16<<<dim3(DD/32, FF/32), xb>>>(w2, tw2, FF, DD);
    f32_to_f16<<<(4*WSZ)/4/256, 256>>>((const float4*)memory, (__half2*)hmem);
    f32_to_f16<<<(16*WSZ)/4/256, 256>>>((const float4*)pos_emb, (__half2*)hbias);

    const dim3 gD(DD / 128, MTOT / 128);        // (8, 32)
    const dim3 gQKV(3 * DD / 128, MTOT / 128);  // (24, 32)
    const dim3 gKV(2 * DD / 128, MTOT / 128);   // (16, 32)
    const dim3 gF(FF / 128, MTOT / 128);        // (32, 32)
    const dim3 gA(LT / 64, HH, BB);

    // ---- self-attention block ----
    rmsnorm_kernel<<<MTOT, 256>>>(x, gamma_sa, (__half2*)bh);
    tc_gemm<5><<<gQKV, 256, TC_SMEM_BYTES>>>(bh, twq_s, o_ks, nullptr, hks, bq, MTOT, 3*DD, DD);
    attn_tc<0><<<gA, 128, ATT_SMEM0>>>(bq, hks, hks + (size_t)SLOT, nullptr, battn);
    tc_gemm<2><<<gD, 256, TC_SMEM_BYTES>>>(battn, two_s, bx1, x, nullptr, nullptr, MTOT, DD, DD);

    // ---- cross-attention block ----
    rmsnorm_kernel<<<MTOT, 256>>>(bx1, gamma_ca, (__half2*)bh);
    tc_gemm<4><<<gD, 256, TC_SMEM_BYTES>>>(bh,   twq_c, nullptr, nullptr, bq, nullptr, MTOT, DD, DD);
    tc_gemm<6><<<gKV, 256, TC_SMEM_BYTES>>>(hmem, twk_c, o_kc, nullptr, hkc, nullptr, MTOT, 2*DD, DD);
    attn_tc<1><<<gA, 128, ATT_SMEM1>>>(bq, hkc, hkc + (size_t)SLOT, hbias, battn);
    tc_gemm<2><<<gD, 256, TC_SMEM_BYTES>>>(battn, two_c, bx2, bx1, nullptr, nullptr, MTOT, DD, DD);

    // ---- FFN block ----
    rmsnorm_kernel<<<MTOT, 256>>>(bx2, gamma_m, (__half2*)bh);
    tc_gemm<3><<<gF, 256, TC_SMEM_BYTES>>>(bh,   tw1, nullptr, nullptr, bffn, nullptr, MTOT, FF, DD);
    tc_gemm<2><<<gD, 256, TC_SMEM_BYTES>>>(bffn, tw2, o_mlp, bx2, nullptr, nullptr, MTOT, DD, FF);
}

// round 16
// speedup vs baseline: 1.8049x; 1.0165x over previous
#include <cuda_runtime.h>
#include <cuda_fp16.h>
#include <cstdint>

// Problem constants
#define BB 4
#define LT 1024
#define LS 1024
#define DD 1024
#define HH 16
#define HD 64
#define FF 4096
#define MTOT (BB*LT)   // 4096 rows

#define SLOT (MTOT*DD)                     // 4M floats
#define WSZ  (DD*DD)                       // 1M (floats or halves, per context)
#define WBASE    ((size_t)5*SLOT + (size_t)MTOT*FF)
#define HKV_BASE (WBASE + 20*(size_t)WSZ)
#define HB_BASE  (HKV_BASE + 8*(size_t)WSZ)
__device__ float g_scratch[HB_BASE + 8*(size_t)WSZ];

// ---------------------------------------------------------------------------
__device__ __forceinline__ void mma_f16(float* d, const uint32_t* a, const uint32_t* b) {
    asm volatile(
        "mma.sync.aligned.m16n8k16.row.col.f32.f16.f16.f32 "
        "{%0,%1,%2,%3}, {%4,%5,%6,%7}, {%8,%9}, {%0,%1,%2,%3};"
        : "+f"(d[0]), "+f"(d[1]), "+f"(d[2]), "+f"(d[3])
        : "r"(a[0]), "r"(a[1]), "r"(a[2]), "r"(a[3]), "r"(b[0]), "r"(b[1]));
}

__device__ __forceinline__ void cp16(uint32_t dst, const void* src) {
    asm volatile("cp.async.cg.shared.global [%0], [%1], 16;" :: "r"(dst), "l"(src));
}

__device__ __forceinline__ void ldsm4(uint32_t* r, uint32_t saddr) {
    asm volatile("ldmatrix.sync.aligned.m8n8.x4.shared.b16 {%0,%1,%2,%3}, [%4];"
        : "=r"(r[0]), "=r"(r[1]), "=r"(r[2]), "=r"(r[3]) : "r"(saddr));
}

__device__ __forceinline__ uint32_t pack_h2(__half lo, __half hi) {
    __half2 h = __halves2half2(lo, hi);
    return *(uint32_t*)&h;
}

// ---------------------------------------------------------------------------
// Preprocess: fp32 -> fp16 elementwise
__global__ void f32_to_f16(const float4* __restrict__ in, __half2* __restrict__ out)
{
    int idx = blockIdx.x * 256 + threadIdx.x;
    float4 v = in[idx];
    out[idx * 2]     = __floats2half2_rn(v.x, v.y);
    out[idx * 2 + 1] = __floats2half2_rn(v.z, v.w);
}

// Preprocess: transpose + fp16: in[K][N] f32 -> out[N][K] half
__global__ void xpose_f16(const float* __restrict__ in, __half* __restrict__ out,
                          int K, int N)
{
    __shared__ float t[32][33];
    int n0 = blockIdx.x * 32, k0 = blockIdx.y * 32;
    int tx = threadIdx.x, ty = threadIdx.y;   // 32 x 8
    #pragma unroll
    for (int i = 0; i < 4; i++)
        t[ty + i * 8][tx] = in[(size_t)(k0 + ty + i * 8) * N + n0 + tx];
    __syncthreads();
    #pragma unroll
    for (int i = 0; i < 4; i++)
        out[(size_t)(n0 + ty + i * 8) * K + k0 + tx] = __float2half_rn(t[tx][ty + i * 8]);
}

// Batched 1024x1024 transpose+fp16; outputs contiguous half arrays (WSZ halves)
struct XP8 { const float* src[8]; };
__global__ void xpose_f16_b8(XP8 p, __half* __restrict__ hwbase)
{
    __shared__ float t[32][33];
    const float* in = p.src[blockIdx.z];
    __half* out = hwbase + (size_t)blockIdx.z * WSZ;
    int n0 = blockIdx.x * 32, k0 = blockIdx.y * 32;
    int tx = threadIdx.x, ty = threadIdx.y;
    #pragma unroll
    for (int i = 0; i < 4; i++)
        t[ty + i * 8][tx] = in[(size_t)(k0 + ty + i * 8) * DD + n0 + tx];
    __syncthreads();
    #pragma unroll
    for (int i = 0; i < 4; i++)
        out[(size_t)(n0 + ty + i * 8) * DD + k0 + tx] = __float2half_rn(t[tx][ty + i * 8]);
}

// ---------------------------------------------------------------------------
// RMSNorm: fp32 in -> fp16 out
__global__ void rmsnorm_kernel(const float* __restrict__ x,
                               const float* __restrict__ g,
                               __half2* __restrict__ out)
{
    __shared__ float red[256];
    int row = blockIdx.x;
    int tid = threadIdx.x;
    const float4* xr = (const float4*)(x + (size_t)row * DD);
    float4 v = xr[tid];
    float ss = v.x*v.x + v.y*v.y + v.z*v.z + v.w*v.w;
    red[tid] = ss;
    __syncthreads();
    #pragma unroll
    for (int s = 128; s > 0; s >>= 1) {
        if (tid < s) red[tid] += red[tid + s];
        __syncthreads();
    }
    float inv = rsqrtf(red[0] * (1.0f/(float)DD) + 1e-6f);
    const float4 gg = ((const float4*)g)[tid];
    __half2* op = out + (size_t)row * (DD/2);
    op[tid * 2]     = __floats2half2_rn(v.x * inv * gg.x, v.y * inv * gg.y);
    op[tid * 2 + 1] = __floats2half2_rn(v.z * inv * gg.z, v.w * inv * gg.w);
}

// ---------------------------------------------------------------------------
// FP16 tensor-core GEMM, ldmatrix fragment loads, 4-stage cp.async pipeline.
// Epilogues: 2 resid f32, 3 relu->half, 4 plain->half,
//            5 self-QKV router, 6 cross-KV router.
#define TC_BK 32
#define AW 20
#define TILE_W (128 * AW)
#define STAGE_W (2 * TILE_W)
#define TC_SMEM_BYTES (4 * STAGE_W * 4)

template<int EPI>
__global__ __launch_bounds__(256)
void tc_gemm(const __half* __restrict__ A, const __half* __restrict__ BT,
             float* __restrict__ C, const float* __restrict__ R,
             __half* __restrict__ Hout, __half* __restrict__ Hq,
             int M, int N, int K)
{
    extern __shared__ float sm[];
    const uint32_t smb = (uint32_t)__cvta_generic_to_shared(sm);

    const int tid  = threadIdx.x;
    const int wid  = tid >> 5;
    const int lane = tid & 31;
    const int g    = lane >> 2;
    const int t    = lane & 3;
    const int wm   = wid & 1;
    const int wn   = wid >> 1;
    const int m0   = blockIdx.y * 128;
    const int n0   = blockIdx.x * 128;

    const int fr = (lane & 7) + ((lane >> 3) & 1) * 8;
    const int fk = ((lane >> 4) & 1) * 4;
    const int br = (lane & 7) + ((lane >> 4) & 1) * 8;
    const int bk = ((lane >> 3) & 1) * 4;
    const uint32_t a_off = (uint32_t)(((wm * 64 + fr) * AW + fk) << 2);
    const uint32_t b_off = (uint32_t)(TILE_W << 2)
                         + (uint32_t)(((wn * 32 + br) * AW + bk) << 2);

    const __half* Ag = A  + (size_t)m0 * K;
    const __half* Bg = BT + (size_t)n0 * K;

    float acc[4][4][4];
    #pragma unroll
    for (int mi = 0; mi < 4; mi++)
        #pragma unroll
        for (int ni = 0; ni < 4; ni++)
            #pragma unroll
            for (int r = 0; r < 4; r++) acc[mi][ni][r] = 0.0f;

    const int NT = K / TC_BK;

    #define G_LOAD(s, k0)                                                     \
    {                                                                         \
        uint32_t ab_ = smb + (uint32_t)((s) * STAGE_W * 4);                   \
        uint32_t bb_ = ab_ + (uint32_t)(TILE_W * 4);                          \
        _Pragma("unroll")                                                     \
        for (int i_ = 0; i_ < 2; i_++) {                                      \
            int idx_ = tid + i_ * 256;                                        \
            int r_ = idx_ >> 2, c_ = idx_ & 3;                                \
            cp16(ab_ + (uint32_t)((r_ * AW + c_ * 4) << 2),                   \
                 Ag + (size_t)r_ * K + (k0) + c_ * 8);                        \
            cp16(bb_ + (uint32_t)((r_ * AW + c_ * 4) << 2),                   \
                 Bg + (size_t)r_ * K + (k0) + c_ * 8);                        \
        }                                                                     \
    }

    G_LOAD(0, 0);
    asm volatile("cp.async.commit_group;");
    G_LOAD(1, TC_BK);
    asm volatile("cp.async.commit_group;");

    for (int kt = 0; kt < NT; kt++) {
        if (kt + 2 < NT) {
            G_LOAD((kt + 2) & 3, (kt + 2) * TC_BK);
        }
        asm volatile("cp.async.commit_group;");
        asm volatile("cp.async.wait_group 2;");
        __syncthreads();

        const uint32_t base  = smb + (uint32_t)((kt & 3) * STAGE_W * 4);
        const uint32_t abase = base + a_off;
        const uint32_t bbase = base + b_off;

        #pragma unroll
        for (int kk = 0; kk < 2; kk++) {
            uint32_t af[4][4];
            uint32_t bfr[2][4];
            #pragma unroll
            for (int mi = 0; mi < 4; mi++)
                ldsm4(af[mi], abase + (uint32_t)(((mi * 16 * AW) + kk * 8) << 2));
            #pragma unroll
            for (int p = 0; p < 2; p++)
                ldsm4(bfr[p], bbase + (uint32_t)(((p * 16 * AW) + kk * 8) << 2));
            #pragma unroll
            for (int mi = 0; mi < 4; mi++)
                #pragma unroll
                for (int ni = 0; ni < 4; ni++)
                    mma_f16(acc[mi][ni], af[mi], &bfr[ni >> 1][(ni & 1) * 2]);
        }
    }
    #undef G_LOAD

    const int mbase = m0 + wm * 64 + g;
    const int nbase = n0 + wn * 32 + 2 * t;

    if (EPI == 5 || EPI == 6) {
        const int sector = n0 >> 10;
        if (EPI == 5 && sector == 0) {
            #pragma unroll
            for (int mi = 0; mi < 4; mi++) {
                #pragma unroll
                for (int ni = 0; ni < 4; ni++) {
                    int n = nbase + ni * 8;
                    #pragma unroll
                    for (int hf = 0; hf < 2; hf++) {
                        int m = mbase + mi * 16 + hf * 8;
                        *(__half2*)&Hq[(size_t)m * DD + n] =
                            __floats2half2_rn(acc[mi][ni][hf * 2], acc[mi][ni][hf * 2 + 1]);
                    }
                }
            }
        } else {
            const int s = (EPI == 5) ? sector - 1 : sector;
            float*  Cb = C    + (size_t)s * SLOT;
            __half* Hb = Hout + (size_t)s * SLOT;
            #pragma unroll
            for (int mi = 0; mi < 4; mi++) {
                #pragma unroll
                for (int ni = 0; ni < 4; ni++) {
                    int n = (nbase + ni * 8) & 1023;
                    int h = n >> 6, d = n & 63;
                    #pragma unroll
                    for (int hf = 0; hf < 2; hf++) {
                        int m = mbase + mi * 16 + hf * 8;
                        int b = m >> 10, l = m & 1023;
                        size_t idx = (((size_t)(b * HH + h) * LT + l) << 6) + d;
                        float v0 = acc[mi][ni][hf * 2], v1 = acc[mi][ni][hf * 2 + 1];
                        *(float2*)&Cb[idx]  = make_float2(v0, v1);
                        *(__half2*)&Hb[idx] = __floats2half2_rn(v0, v1);
                    }
                }
            }
        }
    } else if (EPI == 3 || EPI == 4) {
        #pragma unroll
        for (int mi = 0; mi < 4; mi++) {
            #pragma unroll
            for (int ni = 0; ni < 4; ni++) {
                int n = nbase + ni * 8;
                #pragma unroll
                for (int hf = 0; hf < 2; hf++) {
                    int m = mbase + mi * 16 + hf * 8;
                    size_t off = (size_t)m * N + n;
                    float v0 = acc[mi][ni][hf * 2], v1 = acc[mi][ni][hf * 2 + 1];
                    if (EPI == 3) { v0 = fmaxf(v0, 0.f); v1 = fmaxf(v1, 0.f); }
                    *(__half2*)&Hout[off] = __floats2half2_rn(v0, v1);
                }
            }
        }
    } else {   // EPI == 2
        #pragma unroll
        for (int mi = 0; mi < 4; mi++) {
            #pragma unroll
            for (int ni = 0; ni < 4; ni++) {
                int n = nbase + ni * 8;
                #pragma unroll
                for (int hf = 0; hf < 2; hf++) {
                    int m = mbase + mi * 16 + hf * 8;
                    size_t off = (size_t)m * N + n;
                    float2 v = make_float2(acc[mi][ni][hf * 2], acc[mi][ni][hf * 2 + 1]);
                    float2 r = *(const float2*)(R + off);
                    v.x += r.x; v.y += r.y;
                    *(float2*)(C + off) = v;
                }
            }
        }
    }
}

// ---------------------------------------------------------------------------
// FP16 tensor-core flash attention (m16n8k16, online softmax).
// This round: Q/K/P fragments via ldmatrix (R13-proven patterns); V scalar.
#define ATT_SMEM0 (27648 * 2)
#define ATT_SMEM1 (36864 * 2)

#define LOAD_TILE_H(dstoff, srcptr, srcstride)                                \
    _Pragma("unroll")                                                         \
    for (int i_ = 0; i_ < 4; i_++) {                                          \
        int idx_ = tid + i_ * 128;                                            \
        int r_ = idx_ >> 3, c_ = (idx_ & 7) * 8;                              \
        cp16(sbase + (uint32_t)(((dstoff) + r_ * 72 + c_) * 2),               \
             (srcptr) + (size_t)r_ * (srcstride) + c_);                       \
    }

template<int MODE>
__global__ __launch_bounds__(128)
void attn_tc(const __half* __restrict__ Q, const __half* __restrict__ K,
             const __half* __restrict__ V, const __half* __restrict__ bias,
             __half* __restrict__ O)
{
    extern __shared__ __half smh[];
    const int tid  = threadIdx.x;
    const int wid  = tid >> 5;
    const int lane = tid & 31;
    const int g    = lane >> 2;
    const int t    = lane & 3;
    const int qt   = blockIdx.x;
    const int h    = blockIdx.y;
    const int b    = blockIdx.z;

    const uint32_t sbase = (uint32_t)__cvta_generic_to_shared(smh);

    // ldmatrix lane-address patterns (R13-verified; row stride 36 words)
    const int fr = (lane & 7) + ((lane >> 3) & 1) * 8;
    const int fk = ((lane >> 4) & 1) * 4;
    const int br = (lane & 7) + ((lane >> 4) & 1) * 8;
    const int bk = ((lane >> 3) & 1) * 4;
    const uint32_t q_off = (uint32_t)((((wid * 16 + fr) * 36) + fk) << 2);
    const uint32_t p_off = (uint32_t)(((11520 + (wid * 16 + fr) * 36) + fk) << 2);
    const uint32_t kb_off = (uint32_t)(((br * 36) + bk) << 2);

    const __half* Qg = Q + ((size_t)(b * LT) + qt * 64) * DD + h * HD;
    const __half* Kg = K + ((size_t)(b * HH + h)) * LS * HD;
    const __half* Vg = V + ((size_t)(b * HH + h)) * LS * HD;
    const __half* Bg = (MODE == 1) ? bias + ((size_t)h * LT + qt * 64) * LS : nullptr;

    {
        LOAD_TILE_H(0,     Qg, DD);
        LOAD_TILE_H(4608,  Kg, HD);
        LOAD_TILE_H(13824, Vg, HD);
        if (MODE == 1) {
            LOAD_TILE_H(27648, Bg, LS);
        }
        asm volatile("cp.async.commit_group;");
    }

    float oacc[8][4];
    #pragma unroll
    for (int ni = 0; ni < 8; ni++)
        #pragma unroll
        for (int r = 0; r < 4; r++) oacc[ni][r] = 0.0f;

    float mrow[2] = { -1e30f, -1e30f };
    float lrow[2] = { 0.0f, 0.0f };

    const int ktmax = (MODE == 0) ? qt : (LS / 64 - 1);

    for (int kt = 0; kt <= ktmax; kt++) {
        const int cur = kt & 1;
        __syncthreads();
        if (kt + 1 <= ktmax) {
            const int nk = kt + 1;
            const int koff = cur ? 4608 : 9216;
            const int voff = cur ? 13824 : 18432;
            const __half* kp = Kg + (size_t)nk * 64 * HD;
            const __half* vp = Vg + (size_t)nk * 64 * HD;
            LOAD_TILE_H(koff, kp, HD);
            LOAD_TILE_H(voff, vp, HD);
            if (MODE == 1) {
                const int boff = cur ? 27648 : 32256;
                const __half* bp = Bg + (size_t)nk * 64;
                LOAD_TILE_H(boff, bp, LS);
            }
            asm volatile("cp.async.commit_group;");
            asm volatile("cp.async.wait_group 1;");
        } else {
            asm volatile("cp.async.wait_group 0;");
        }
        __syncthreads();

        const int koff = cur ? 9216 : 4608;
        const int voff = cur ? 18432 : 13824;
        const int boff = cur ? 32256 : 27648;

        // ---- S = Q K^T  (ldmatrix fragments) ----
        float sacc[8][4];
        #pragma unroll
        for (int ni = 0; ni < 8; ni++)
            #pragma unroll
            for (int r = 0; r < 4; r++) sacc[ni][r] = 0.0f;

        {
            const uint32_t kbase = sbase + (uint32_t)(koff * 2) + kb_off;
            #pragma unroll
            for (int kk = 0; kk < 4; kk++) {
                uint32_t a[4];
                ldsm4(a, sbase + q_off + (uint32_t)((kk * 8) << 2));
                #pragma unroll
                for (int p = 0; p < 4; p++) {
                    uint32_t bb[4];
                    ldsm4(bb, kbase + (uint32_t)(((p * 16 * 36) + kk * 8) << 2));
                    mma_f16(sacc[2 * p],     a, &bb[0]);
                    mma_f16(sacc[2 * p + 1], a, &bb[2]);
                }
            }
        }

        // ---- softmax ----
        #pragma unroll
        for (int hf = 0; hf < 2; hf++) {
            const int row_l = wid * 16 + g + hf * 8;
            float mx = -1e30f;
            #pragma unroll
            for (int ni = 0; ni < 8; ni++) {
                #pragma unroll
                for (int c = 0; c < 2; c++) {
                    float v = sacc[ni][hf * 2 + c] * 0.125f;
                    if (MODE == 0) {
                        if (kt == qt) {
                            int keyl = ni * 8 + 2 * t + c;
                            if (keyl > row_l) v = -1e30f;
                        }
                    } else {
                        v += __half2float(smh[boff + row_l * 72 + ni * 8 + 2 * t + c]);
                    }
                    sacc[ni][hf * 2 + c] = v;
                    mx = fmaxf(mx, v);
                }
            }
            mx = fmaxf(mx, __shfl_xor_sync(0xffffffffu, mx, 1));
            mx = fmaxf(mx, __shfl_xor_sync(0xffffffffu, mx, 2));
            float mnew = fmaxf(mrow[hf], mx);
            float corr = __expf(mrow[hf] - mnew);
            mrow[hf] = mnew;
            float sum = 0.0f;
            #pragma unroll
            for (int ni = 0; ni < 8; ni++) {
                float p0 = __expf(sacc[ni][hf * 2]     - mnew);
                float p1 = __expf(sacc[ni][hf * 2 + 1] - mnew);
                sum += p0 + p1;
                sacc[ni][hf * 2]     = p0;
                sacc[ni][hf * 2 + 1] = p1;
            }
            sum += __shfl_xor_sync(0xffffffffu, sum, 1);
            sum += __shfl_xor_sync(0xffffffffu, sum, 2);
            lrow[hf] = lrow[hf] * corr + sum;
            #pragma unroll
            for (int ni = 0; ni < 8; ni++) {
                oacc[ni][hf * 2]     *= corr;
                oacc[ni][hf * 2 + 1] *= corr;
                *(__half2*)&smh[23040 + row_l * 72 + ni * 8 + 2 * t] =
                    __floats2half2_rn(sacc[ni][hf * 2], sacc[ni][hf * 2 + 1]);
            }
        }
        __syncwarp();

        // ---- O += P V  (P via ldmatrix; V scalar+pack) ----
        {
            const __half* vb = smh + voff + (2 * t) * 72 + g;
            #pragma unroll
            for (int kk = 0; kk < 4; kk++) {
                uint32_t a[4];
                ldsm4(a, sbase + p_off + (uint32_t)((kk * 8) << 2));
                const __half* vk = vb + kk * 1152;
                #pragma unroll
                for (int ni = 0; ni < 8; ni++) {
                    uint32_t bf[2];
                    bf[0] = pack_h2(vk[ni * 8],       vk[72 + ni * 8]);
                    bf[1] = pack_h2(vk[576 + ni * 8], vk[648 + ni * 8]);
                    mma_f16(oacc[ni], a, bf);
                }
            }
        }
        __syncwarp();
    }

    // ---- normalize + write O as fp16 ----
    #pragma unroll
    for (int hf = 0; hf < 2; hf++) {
        const int row_l = wid * 16 + g + hf * 8;
        const int qg = qt * 64 + row_l;
        const float invl = 1.0f / lrow[hf];
        __half* op = O + ((size_t)(b * LT) + qg) * DD + h * HD;
        #pragma unroll
        for (int ni = 0; ni < 8; ni++) {
            *(__half2*)(op + ni * 8 + 2 * t) =
                __floats2half2_rn(oacc[ni][hf * 2] * invl, oacc[ni][hf * 2 + 1] * invl);
        }
    }
}

// ---------------------------------------------------------------------------
extern "C" void kernel_launch(void* const* d_in, const int* in_sizes, int n_in,
                              void* d_out, int out_size)
{
    const float* x        = (const float*)d_in[0];
    const float* memory   = (const float*)d_in[1];
    const float* pos_emb  = (const float*)d_in[2];
    const float* gamma_sa = (const float*)d_in[4];
    const float* wq_s     = (const float*)d_in[5];
    const float* wk_s     = (const float*)d_in[6];
    const float* wv_s     = (const float*)d_in[7];
    const float* wo_s     = (const float*)d_in[8];
    const float* gamma_ca = (const float*)d_in[9];
    const float* wq_c     = (const float*)d_in[10];
    const float* wk_c     = (const float*)d_in[11];
    const float* wv_c     = (const float*)d_in[12];
    const float* wo_c     = (const float*)d_in[13];
    const float* gamma_m  = (const float*)d_in[14];
    const float* w1       = (const float*)d_in[15];
    const float* w2       = (const float*)d_in[16];

    float* scratch = nullptr;
    cudaGetSymbolAddress((void**)&scratch, g_scratch);
    __half* bh    = (__half*)(scratch);
    __half* bq    = (__half*)(scratch + (size_t)1 * SLOT);
    __half* battn = (__half*)(scratch + (size_t)2 * SLOT);
    float*  bx1   = scratch + (size_t)3 * SLOT;
    float*  bx2   = scratch + (size_t)4 * SLOT;
    __half* bffn  = (__half*)(scratch + (size_t)5 * SLOT);

    __half* hw    = (__half*)(scratch + WBASE);
    __half* twq_s = hw + 0 * (size_t)WSZ;
    __half* two_s = hw + 3 * (size_t)WSZ;
    __half* twq_c = hw + 4 * (size_t)WSZ;
    __half* twk_c = hw + 5 * (size_t)WSZ;
    __half* two_c = hw + 7 * (size_t)WSZ;
    __half* tw1   = hw + 8  * (size_t)WSZ;
    __half* tw2   = hw + 12 * (size_t)WSZ;
    __half* hmem  = hw + 16 * (size_t)WSZ;

    float*  hkvb  = scratch + HKV_BASE;
    __half* hks   = (__half*)(hkvb);
    __half* hkc   = (__half*)(hkvb + 2 * (size_t)(SLOT/2));
    __half* hbias = (__half*)(scratch + HB_BASE);

    float* out   = (float*)d_out;
    float* o_mlp = out;
    float* o_ks  = out + (size_t)1 * SLOT;
    float* o_kc  = out + (size_t)3 * SLOT;

    cudaFuncSetAttribute(tc_gemm<2>, cudaFuncAttributeMaxDynamicSharedMemorySize, TC_SMEM_BYTES);
    cudaFuncSetAttribute(tc_gemm<3>, cudaFuncAttributeMaxDynamicSharedMemorySize, TC_SMEM_BYTES);
    cudaFuncSetAttribute(tc_gemm<4>, cudaFuncAttributeMaxDynamicSharedMemorySize, TC_SMEM_BYTES);
    cudaFuncSetAttribute(tc_gemm<5>, cudaFuncAttributeMaxDynamicSharedMemorySize, TC_SMEM_BYTES);
    cudaFuncSetAttribute(tc_gemm<6>, cudaFuncAttributeMaxDynamicSharedMemorySize, TC_SMEM_BYTES);
    cudaFuncSetAttribute(attn_tc<0>, cudaFuncAttributeMaxDynamicSharedMemorySize, ATT_SMEM0);
    cudaFuncSetAttribute(attn_tc<1>, cudaFuncAttributeMaxDynamicSharedMemorySize, ATT_SMEM1);

    // ---- preprocess ----
    {
        XP8 p;
        p.src[0] = wq_s; p.src[1] = wk_s; p.src[2] = wv_s; p.src[3] = wo_s;
        p.src[4] = wq_c; p.src[5] = wk_c; p.src[6] = wv_c; p.src[7] = wo_c;
        xpose_f16_b8<<<dim3(DD/32, DD/32, 8), dim3(32, 8)>>>(p, hw);
    }
    const dim3 xb(32, 8);
    xpose_f16<<<dim3(FF/32, DD/32), xb>>>(w1, tw1, DD, FF);
    xpose_f16<<<dim3(DD/32, FF/32), xb>>>(w2, tw2, FF, DD);
    f32_to_f16<<<(4*WSZ)/4/256, 256>>>((const float4*)memory, (__half2*)hmem);
    f32_to_f16<<<(16*WSZ)/4/256, 256>>>((const float4*)pos_emb, (__half2*)hbias);

    const dim3 gD(DD / 128, MTOT / 128);        // (8, 32)
    const dim3 gQKV(3 * DD / 128, MTOT / 128);  // (24, 32)
    const dim3 gKV(2 * DD / 128, MTOT / 128);   // (16, 32)
    const dim3 gF(FF / 128, MTOT / 128);        // (32, 32)
    const dim3 gA(LT / 64, HH, BB);

    // ---- self-attention block ----
    rmsnorm_kernel<<<MTOT, 256>>>(x, gamma_sa, (__half2*)bh);
    tc_gemm<5><<<gQKV, 256, TC_SMEM_BYTES>>>(bh, twq_s, o_ks, nullptr, hks, bq, MTOT, 3*DD, DD);
    attn_tc<0><<<gA, 128, ATT_SMEM0>>>(bq, hks, hks + (size_t)SLOT, nullptr, battn);
    tc_gemm<2><<<gD, 256, TC_SMEM_BYTES>>>(battn, two_s, bx1, x, nullptr, nullptr, MTOT, DD, DD);

    // ---- cross-attention block ----
    rmsnorm_kernel<<<MTOT, 256>>>(bx1, gamma_ca, (__half2*)bh);
    tc_gemm<4><<<gD, 256, TC_SMEM_BYTES>>>(bh,   twq_c, nullptr, nullptr, bq, nullptr, MTOT, DD, DD);
    tc_gemm<6><<<gKV, 256, TC_SMEM_BYTES>>>(hmem, twk_c, o_kc, nullptr, hkc, nullptr, MTOT, 2*DD, DD);
    attn_tc<1><<<gA, 128, ATT_SMEM1>>>(bq, hkc, hkc + (size_t)SLOT, hbias, battn);
    tc_gemm<2><<<gD, 256, TC_SMEM_BYTES>>>(battn, two_c, bx2, bx1, nullptr, nullptr, MTOT, DD, DD);

    // ---- FFN block ----
    rmsnorm_kernel<<<MTOT, 256>>>(bx2, gamma_m, (__half2*)bh);
    tc_gemm<3><<<gF, 256, TC_SMEM_BYTES>>>(bh,   tw1, nullptr, nullptr, bffn, nullptr, MTOT, FF, DD);
    tc_gemm<2><<<gD, 256, TC_SMEM_BYTES>>>(bffn, tw2, o_mlp, bx2, nullptr, nullptr, MTOT, DD, FF);
}

// round 17
// speedup vs baseline: 1.8904x; 1.0474x over previous
#include <cuda_runtime.h>
#include <cuda_fp16.h>
#include <cstdint>

// Problem constants
#define BB 4
#define LT 1024
#define LS 1024
#define DD 1024
#define HH 16
#define HD 64
#define FF 4096
#define MTOT (BB*LT)   // 4096 rows

#define SLOT (MTOT*DD)                     // 4M floats
#define WSZ  (DD*DD)                       // 1M (floats or halves, per context)
#define WBASE    ((size_t)5*SLOT + (size_t)MTOT*FF)
#define HKV_BASE (WBASE + 20*(size_t)WSZ)
#define HB_BASE  (HKV_BASE + 8*(size_t)WSZ)
__device__ float g_scratch[HB_BASE + 8*(size_t)WSZ];

// ---------------------------------------------------------------------------
__device__ __forceinline__ void mma_f16(float* d, const uint32_t* a, const uint32_t* b) {
    asm volatile(
        "mma.sync.aligned.m16n8k16.row.col.f32.f16.f16.f32 "
        "{%0,%1,%2,%3}, {%4,%5,%6,%7}, {%8,%9}, {%0,%1,%2,%3};"
        : "+f"(d[0]), "+f"(d[1]), "+f"(d[2]), "+f"(d[3])
        : "r"(a[0]), "r"(a[1]), "r"(a[2]), "r"(a[3]), "r"(b[0]), "r"(b[1]));
}

__device__ __forceinline__ void cp16(uint32_t dst, const void* src) {
    asm volatile("cp.async.cg.shared.global [%0], [%1], 16;" :: "r"(dst), "l"(src));
}

__device__ __forceinline__ void ldsm4(uint32_t* r, uint32_t saddr) {
    asm volatile("ldmatrix.sync.aligned.m8n8.x4.shared.b16 {%0,%1,%2,%3}, [%4];"
        : "=r"(r[0]), "=r"(r[1]), "=r"(r[2]), "=r"(r[3]) : "r"(saddr));
}

__device__ __forceinline__ void ldsm4_t(uint32_t* r, uint32_t saddr) {
    asm volatile("ldmatrix.sync.aligned.m8n8.x4.trans.shared.b16 {%0,%1,%2,%3}, [%4];"
        : "=r"(r[0]), "=r"(r[1]), "=r"(r[2]), "=r"(r[3]) : "r"(saddr));
}

// ---------------------------------------------------------------------------
// Preprocess: fp32 -> fp16 elementwise
__global__ void f32_to_f16(const float4* __restrict__ in, __half2* __restrict__ out)
{
    int idx = blockIdx.x * 256 + threadIdx.x;
    float4 v = in[idx];
    out[idx * 2]     = __floats2half2_rn(v.x, v.y);
    out[idx * 2 + 1] = __floats2half2_rn(v.z, v.w);
}

// Preprocess: transpose + fp16: in[K][N] f32 -> out[N][K] half
__global__ void xpose_f16(const float* __restrict__ in, __half* __restrict__ out,
                          int K, int N)
{
    __shared__ float t[32][33];
    int n0 = blockIdx.x * 32, k0 = blockIdx.y * 32;
    int tx = threadIdx.x, ty = threadIdx.y;   // 32 x 8
    #pragma unroll
    for (int i = 0; i < 4; i++)
        t[ty + i * 8][tx] = in[(size_t)(k0 + ty + i * 8) * N + n0 + tx];
    __syncthreads();
    #pragma unroll
    for (int i = 0; i < 4; i++)
        out[(size_t)(n0 + ty + i * 8) * K + k0 + tx] = __float2half_rn(t[tx][ty + i * 8]);
}

// Batched 1024x1024 transpose+fp16; outputs contiguous half arrays (WSZ halves)
struct XP8 { const float* src[8]; };
__global__ void xpose_f16_b8(XP8 p, __half* __restrict__ hwbase)
{
    __shared__ float t[32][33];
    const float* in = p.src[blockIdx.z];
    __half* out = hwbase + (size_t)blockIdx.z * WSZ;
    int n0 = blockIdx.x * 32, k0 = blockIdx.y * 32;
    int tx = threadIdx.x, ty = threadIdx.y;
    #pragma unroll
    for (int i = 0; i < 4; i++)
        t[ty + i * 8][tx] = in[(size_t)(k0 + ty + i * 8) * DD + n0 + tx];
    __syncthreads();
    #pragma unroll
    for (int i = 0; i < 4; i++)
        out[(size_t)(n0 + ty + i * 8) * DD + k0 + tx] = __float2half_rn(t[tx][ty + i * 8]);
}

// ---------------------------------------------------------------------------
// RMSNorm: fp32 in -> fp16 out
__global__ void rmsnorm_kernel(const float* __restrict__ x,
                               const float* __restrict__ g,
                               __half2* __restrict__ out)
{
    __shared__ float red[256];
    int row = blockIdx.x;
    int tid = threadIdx.x;
    const float4* xr = (const float4*)(x + (size_t)row * DD);
    float4 v = xr[tid];
    float ss = v.x*v.x + v.y*v.y + v.z*v.z + v.w*v.w;
    red[tid] = ss;
    __syncthreads();
    #pragma unroll
    for (int s = 128; s > 0; s >>= 1) {
        if (tid < s) red[tid] += red[tid + s];
        __syncthreads();
    }
    float inv = rsqrtf(red[0] * (1.0f/(float)DD) + 1e-6f);
    const float4 gg = ((const float4*)g)[tid];
    __half2* op = out + (size_t)row * (DD/2);
    op[tid * 2]     = __floats2half2_rn(v.x * inv * gg.x, v.y * inv * gg.y);
    op[tid * 2 + 1] = __floats2half2_rn(v.z * inv * gg.z, v.w * inv * gg.w);
}

// ---------------------------------------------------------------------------
// FP16 tensor-core GEMM, ldmatrix fragment loads, 4-stage cp.async pipeline.
// Epilogues: 2 resid f32, 3 relu->half, 4 plain->half,
//            5 self-QKV router, 6 cross-KV router.
#define TC_BK 32
#define AW 20
#define TILE_W (128 * AW)
#define STAGE_W (2 * TILE_W)
#define TC_SMEM_BYTES (4 * STAGE_W * 4)

template<int EPI>
__global__ __launch_bounds__(256)
void tc_gemm(const __half* __restrict__ A, const __half* __restrict__ BT,
             float* __restrict__ C, const float* __restrict__ R,
             __half* __restrict__ Hout, __half* __restrict__ Hq,
             int M, int N, int K)
{
    extern __shared__ float sm[];
    const uint32_t smb = (uint32_t)__cvta_generic_to_shared(sm);

    const int tid  = threadIdx.x;
    const int wid  = tid >> 5;
    const int lane = tid & 31;
    const int g    = lane >> 2;
    const int t    = lane & 3;
    const int wm   = wid & 1;
    const int wn   = wid >> 1;
    const int m0   = blockIdx.y * 128;
    const int n0   = blockIdx.x * 128;

    const int fr = (lane & 7) + ((lane >> 3) & 1) * 8;
    const int fk = ((lane >> 4) & 1) * 4;
    const int br = (lane & 7) + ((lane >> 4) & 1) * 8;
    const int bk = ((lane >> 3) & 1) * 4;
    const uint32_t a_off = (uint32_t)(((wm * 64 + fr) * AW + fk) << 2);
    const uint32_t b_off = (uint32_t)(TILE_W << 2)
                         + (uint32_t)(((wn * 32 + br) * AW + bk) << 2);

    const __half* Ag = A  + (size_t)m0 * K;
    const __half* Bg = BT + (size_t)n0 * K;

    float acc[4][4][4];
    #pragma unroll
    for (int mi = 0; mi < 4; mi++)
        #pragma unroll
        for (int ni = 0; ni < 4; ni++)
            #pragma unroll
            for (int r = 0; r < 4; r++) acc[mi][ni][r] = 0.0f;

    const int NT = K / TC_BK;

    #define G_LOAD(s, k0)                                                     \
    {                                                                         \
        uint32_t ab_ = smb + (uint32_t)((s) * STAGE_W * 4);                   \
        uint32_t bb_ = ab_ + (uint32_t)(TILE_W * 4);                          \
        _Pragma("unroll")                                                     \
        for (int i_ = 0; i_ < 2; i_++) {                                      \
            int idx_ = tid + i_ * 256;                                        \
            int r_ = idx_ >> 2, c_ = idx_ & 3;                                \
            cp16(ab_ + (uint32_t)((r_ * AW + c_ * 4) << 2),                   \
                 Ag + (size_t)r_ * K + (k0) + c_ * 8);                        \
            cp16(bb_ + (uint32_t)((r_ * AW + c_ * 4) << 2),                   \
                 Bg + (size_t)r_ * K + (k0) + c_ * 8);                        \
        }                                                                     \
    }

    G_LOAD(0, 0);
    asm volatile("cp.async.commit_group;");
    G_LOAD(1, TC_BK);
    asm volatile("cp.async.commit_group;");

    for (int kt = 0; kt < NT; kt++) {
        if (kt + 2 < NT) {
            G_LOAD((kt + 2) & 3, (kt + 2) * TC_BK);
        }
        asm volatile("cp.async.commit_group;");
        asm volatile("cp.async.wait_group 2;");
        __syncthreads();

        const uint32_t base  = smb + (uint32_t)((kt & 3) * STAGE_W * 4);
        const uint32_t abase = base + a_off;
        const uint32_t bbase = base + b_off;

        #pragma unroll
        for (int kk = 0; kk < 2; kk++) {
            uint32_t af[4][4];
            uint32_t bfr[2][4];
            #pragma unroll
            for (int mi = 0; mi < 4; mi++)
                ldsm4(af[mi], abase + (uint32_t)(((mi * 16 * AW) + kk * 8) << 2));
            #pragma unroll
            for (int p = 0; p < 2; p++)
                ldsm4(bfr[p], bbase + (uint32_t)(((p * 16 * AW) + kk * 8) << 2));
            #pragma unroll
            for (int mi = 0; mi < 4; mi++)
                #pragma unroll
                for (int ni = 0; ni < 4; ni++)
                    mma_f16(acc[mi][ni], af[mi], &bfr[ni >> 1][(ni & 1) * 2]);
        }
    }
    #undef G_LOAD

    const int mbase = m0 + wm * 64 + g;
    const int nbase = n0 + wn * 32 + 2 * t;

    if (EPI == 5 || EPI == 6) {
        const int sector = n0 >> 10;
        if (EPI == 5 && sector == 0) {
            #pragma unroll
            for (int mi = 0; mi < 4; mi++) {
                #pragma unroll
                for (int ni = 0; ni < 4; ni++) {
                    int n = nbase + ni * 8;
                    #pragma unroll
                    for (int hf = 0; hf < 2; hf++) {
                        int m = mbase + mi * 16 + hf * 8;
                        *(__half2*)&Hq[(size_t)m * DD + n] =
                            __floats2half2_rn(acc[mi][ni][hf * 2], acc[mi][ni][hf * 2 + 1]);
                    }
                }
            }
        } else {
            const int s = (EPI == 5) ? sector - 1 : sector;
            float*  Cb = C    + (size_t)s * SLOT;
            __half* Hb = Hout + (size_t)s * SLOT;
            #pragma unroll
            for (int mi = 0; mi < 4; mi++) {
                #pragma unroll
                for (int ni = 0; ni < 4; ni++) {
                    int n = (nbase + ni * 8) & 1023;
                    int h = n >> 6, d = n & 63;
                    #pragma unroll
                    for (int hf = 0; hf < 2; hf++) {
                        int m = mbase + mi * 16 + hf * 8;
                        int b = m >> 10, l = m & 1023;
                        size_t idx = (((size_t)(b * HH + h) * LT + l) << 6) + d;
                        float v0 = acc[mi][ni][hf * 2], v1 = acc[mi][ni][hf * 2 + 1];
                        *(float2*)&Cb[idx]  = make_float2(v0, v1);
                        *(__half2*)&Hb[idx] = __floats2half2_rn(v0, v1);
                    }
                }
            }
        }
    } else if (EPI == 3 || EPI == 4) {
        #pragma unroll
        for (int mi = 0; mi < 4; mi++) {
            #pragma unroll
            for (int ni = 0; ni < 4; ni++) {
                int n = nbase + ni * 8;
                #pragma unroll
                for (int hf = 0; hf < 2; hf++) {
                    int m = mbase + mi * 16 + hf * 8;
                    size_t off = (size_t)m * N + n;
                    float v0 = acc[mi][ni][hf * 2], v1 = acc[mi][ni][hf * 2 + 1];
                    if (EPI == 3) { v0 = fmaxf(v0, 0.f); v1 = fmaxf(v1, 0.f); }
                    *(__half2*)&Hout[off] = __floats2half2_rn(v0, v1);
                }
            }
        }
    } else {   // EPI == 2
        #pragma unroll
        for (int mi = 0; mi < 4; mi++) {
            #pragma unroll
            for (int ni = 0; ni < 4; ni++) {
                int n = nbase + ni * 8;
                #pragma unroll
                for (int hf = 0; hf < 2; hf++) {
                    int m = mbase + mi * 16 + hf * 8;
                    size_t off = (size_t)m * N + n;
                    float2 v = make_float2(acc[mi][ni][hf * 2], acc[mi][ni][hf * 2 + 1]);
                    float2 r = *(const float2*)(R + off);
                    v.x += r.x; v.y += r.y;
                    *(float2*)(C + off) = v;
                }
            }
        }
    }
}

// ---------------------------------------------------------------------------
// FP16 tensor-core flash attention (m16n8k16, online softmax).
// Q/K/P via ldmatrix; V via ldmatrix.trans (this round).
#define ATT_SMEM0 (27648 * 2)
#define ATT_SMEM1 (36864 * 2)

#define LOAD_TILE_H(dstoff, srcptr, srcstride)                                \
    _Pragma("unroll")                                                         \
    for (int i_ = 0; i_ < 4; i_++) {                                          \
        int idx_ = tid + i_ * 128;                                            \
        int r_ = idx_ >> 3, c_ = (idx_ & 7) * 8;                              \
        cp16(sbase + (uint32_t)(((dstoff) + r_ * 72 + c_) * 2),               \
             (srcptr) + (size_t)r_ * (srcstride) + c_);                       \
    }

template<int MODE>
__global__ __launch_bounds__(128)
void attn_tc(const __half* __restrict__ Q, const __half* __restrict__ K,
             const __half* __restrict__ V, const __half* __restrict__ bias,
             __half* __restrict__ O)
{
    extern __shared__ __half smh[];
    const int tid  = threadIdx.x;
    const int wid  = tid >> 5;
    const int lane = tid & 31;
    const int g    = lane >> 2;
    const int t    = lane & 3;
    const int qt   = blockIdx.x;
    const int h    = blockIdx.y;
    const int b    = blockIdx.z;

    const uint32_t sbase = (uint32_t)__cvta_generic_to_shared(smh);

    // ldmatrix lane-address patterns (verified; row stride 36 words)
    const int fr = (lane & 7) + ((lane >> 3) & 1) * 8;
    const int fk = ((lane >> 4) & 1) * 4;
    const int br = (lane & 7) + ((lane >> 4) & 1) * 8;
    const int bk = ((lane >> 3) & 1) * 4;
    const uint32_t q_off = (uint32_t)((((wid * 16 + fr) * 36) + fk) << 2);
    const uint32_t p_off = (uint32_t)(((11520 + (wid * 16 + fr) * 36) + fk) << 2);
    const uint32_t kb_off = (uint32_t)(((br * 36) + bk) << 2);
    // V trans pattern: matrices (k-low,n-low),(k-high,n-low),(k-low,n-high),(k-high,n-high)
    const int vr = (lane & 7) + ((lane >> 3) & 1) * 8;
    const int vc = ((lane >> 4) & 1) * 8;
    const uint32_t vb_off = (uint32_t)((vr * 72 + vc) * 2);

    const __half* Qg = Q + ((size_t)(b * LT) + qt * 64) * DD + h * HD;
    const __half* Kg = K + ((size_t)(b * HH + h)) * LS * HD;
    const __half* Vg = V + ((size_t)(b * HH + h)) * LS * HD;
    const __half* Bg = (MODE == 1) ? bias + ((size_t)h * LT + qt * 64) * LS : nullptr;

    {
        LOAD_TILE_H(0,     Qg, DD);
        LOAD_TILE_H(4608,  Kg, HD);
        LOAD_TILE_H(13824, Vg, HD);
        if (MODE == 1) {
            LOAD_TILE_H(27648, Bg, LS);
        }
        asm volatile("cp.async.commit_group;");
    }

    float oacc[8][4];
    #pragma unroll
    for (int ni = 0; ni < 8; ni++)
        #pragma unroll
        for (int r = 0; r < 4; r++) oacc[ni][r] = 0.0f;

    float mrow[2] = { -1e30f, -1e30f };
    float lrow[2] = { 0.0f, 0.0f };

    const int ktmax = (MODE == 0) ? qt : (LS / 64 - 1);

    for (int kt = 0; kt <= ktmax; kt++) {
        const int cur = kt & 1;
        __syncthreads();
        if (kt + 1 <= ktmax) {
            const int nk = kt + 1;
            const int koff = cur ? 4608 : 9216;
            const int voff = cur ? 13824 : 18432;
            const __half* kp = Kg + (size_t)nk * 64 * HD;
            const __half* vp = Vg + (size_t)nk * 64 * HD;
            LOAD_TILE_H(koff, kp, HD);
            LOAD_TILE_H(voff, vp, HD);
            if (MODE == 1) {
                const int boff = cur ? 27648 : 32256;
                const __half* bp = Bg + (size_t)nk * 64;
                LOAD_TILE_H(boff, bp, LS);
            }
            asm volatile("cp.async.commit_group;");
            asm volatile("cp.async.wait_group 1;");
        } else {
            asm volatile("cp.async.wait_group 0;");
        }
        __syncthreads();

        const int koff = cur ? 9216 : 4608;
        const int voff = cur ? 18432 : 13824;
        const int boff = cur ? 32256 : 27648;

        // ---- S = Q K^T  (ldmatrix fragments) ----
        float sacc[8][4];
        #pragma unroll
        for (int ni = 0; ni < 8; ni++)
            #pragma unroll
            for (int r = 0; r < 4; r++) sacc[ni][r] = 0.0f;

        {
            const uint32_t kbase = sbase + (uint32_t)(koff * 2) + kb_off;
            #pragma unroll
            for (int kk = 0; kk < 4; kk++) {
                uint32_t a[4];
                ldsm4(a, sbase + q_off + (uint32_t)((kk * 8) << 2));
                #pragma unroll
                for (int p = 0; p < 4; p++) {
                    uint32_t bb[4];
                    ldsm4(bb, kbase + (uint32_t)(((p * 16 * 36) + kk * 8) << 2));
                    mma_f16(sacc[2 * p],     a, &bb[0]);
                    mma_f16(sacc[2 * p + 1], a, &bb[2]);
                }
            }
        }

        // ---- softmax ----
        #pragma unroll
        for (int hf = 0; hf < 2; hf++) {
            const int row_l = wid * 16 + g + hf * 8;
            float mx = -1e30f;
            #pragma unroll
            for (int ni = 0; ni < 8; ni++) {
                #pragma unroll
                for (int c = 0; c < 2; c++) {
                    float v = sacc[ni][hf * 2 + c] * 0.125f;
                    if (MODE == 0) {
                        if (kt == qt) {
                            int keyl = ni * 8 + 2 * t + c;
                            if (keyl > row_l) v = -1e30f;
                        }
                    } else {
                        v += __half2float(smh[boff + row_l * 72 + ni * 8 + 2 * t + c]);
                    }
                    sacc[ni][hf * 2 + c] = v;
                    mx = fmaxf(mx, v);
                }
            }
            mx = fmaxf(mx, __shfl_xor_sync(0xffffffffu, mx, 1));
            mx = fmaxf(mx, __shfl_xor_sync(0xffffffffu, mx, 2));
            float mnew = fmaxf(mrow[hf], mx);
            float corr = __expf(mrow[hf] - mnew);
            mrow[hf] = mnew;
            float sum = 0.0f;
            #pragma unroll
            for (int ni = 0; ni < 8; ni++) {
                float p0 = __expf(sacc[ni][hf * 2]     - mnew);
                float p1 = __expf(sacc[ni][hf * 2 + 1] - mnew);
                sum += p0 + p1;
                sacc[ni][hf * 2]     = p0;
                sacc[ni][hf * 2 + 1] = p1;
            }
            sum += __shfl_xor_sync(0xffffffffu, sum, 1);
            sum += __shfl_xor_sync(0xffffffffu, sum, 2);
            lrow[hf] = lrow[hf] * corr + sum;
            #pragma unroll
            for (int ni = 0; ni < 8; ni++) {
                oacc[ni][hf * 2]     *= corr;
                oacc[ni][hf * 2 + 1] *= corr;
                *(__half2*)&smh[23040 + row_l * 72 + ni * 8 + 2 * t] =
                    __floats2half2_rn(sacc[ni][hf * 2], sacc[ni][hf * 2 + 1]);
            }
        }
        __syncwarp();

        // ---- O += P V  (P via ldmatrix, V via ldmatrix.trans) ----
        {
            const uint32_t vbase = sbase + (uint32_t)(voff * 2) + vb_off;
            #pragma unroll
            for (int kk = 0; kk < 4; kk++) {
                uint32_t a[4];
                ldsm4(a, sbase + p_off + (uint32_t)((kk * 8) << 2));
                #pragma unroll
                for (int np = 0; np < 4; np++) {
                    uint32_t bb[4];
                    ldsm4_t(bb, vbase + (uint32_t)((kk * 16 * 72 + np * 16) * 2));
                    mma_f16(oacc[2 * np],     a, &bb[0]);
                    mma_f16(oacc[2 * np + 1], a, &bb[2]);
                }
            }
        }
        __syncwarp();
    }

    // ---- normalize + write O as fp16 ----
    #pragma unroll
    for (int hf = 0; hf < 2; hf++) {
        const int row_l = wid * 16 + g + hf * 8;
        const int qg = qt * 64 + row_l;
        const float invl = 1.0f / lrow[hf];
        __half* op = O + ((size_t)(b * LT) + qg) * DD + h * HD;
        #pragma unroll
        for (int ni = 0; ni < 8; ni++) {
            *(__half2*)(op + ni * 8 + 2 * t) =
                __floats2half2_rn(oacc[ni][hf * 2] * invl, oacc[ni][hf * 2 + 1] * invl);
        }
    }
}

// ---------------------------------------------------------------------------
extern "C" void kernel_launch(void* const* d_in, const int* in_sizes, int n_in,
                              void* d_out, int out_size)
{
    const float* x        = (const float*)d_in[0];
    const float* memory   = (const float*)d_in[1];
    const float* pos_emb  = (const float*)d_in[2];
    const float* gamma_sa = (const float*)d_in[4];
    const float* wq_s     = (const float*)d_in[5];
    const float* wk_s     = (const float*)d_in[6];
    const float* wv_s     = (const float*)d_in[7];
    const float* wo_s     = (const float*)d_in[8];
    const float* gamma_ca = (const float*)d_in[9];
    const float* wq_c     = (const float*)d_in[10];
    const float* wk_c     = (const float*)d_in[11];
    const float* wv_c     = (const float*)d_in[12];
    const float* wo_c     = (const float*)d_in[13];
    const float* gamma_m  = (const float*)d_in[14];
    const float* w1       = (const float*)d_in[15];
    const float* w2       = (const float*)d_in[16];

    float* scratch = nullptr;
    cudaGetSymbolAddress((void**)&scratch, g_scratch);
    __half* bh    = (__half*)(scratch);
    __half* bq    = (__half*)(scratch + (size_t)1 * SLOT);
    __half* battn = (__half*)(scratch + (size_t)2 * SLOT);
    float*  bx1   = scratch + (size_t)3 * SLOT;
    float*  bx2   = scratch + (size_t)4 * SLOT;
    __half* bffn  = (__half*)(scratch + (size_t)5 * SLOT);

    __half* hw    = (__half*)(scratch + WBASE);
    __half* twq_s = hw + 0 * (size_t)WSZ;
    __half* two_s = hw + 3 * (size_t)WSZ;
    __half* twq_c = hw + 4 * (size_t)WSZ;
    __half* twk_c = hw + 5 * (size_t)WSZ;
    __half* two_c = hw + 7 * (size_t)WSZ;
    __half* tw1   = hw + 8  * (size_t)WSZ;
    __half* tw2   = hw + 12 * (size_t)WSZ;
    __half* hmem  = hw + 16 * (size_t)WSZ;

    float*  hkvb  = scratch + HKV_BASE;
    __half* hks   = (__half*)(hkvb);
    __half* hkc   = (__half*)(hkvb + 2 * (size_t)(SLOT/2));
    __half* hbias = (__half*)(scratch + HB_BASE);

    float* out   = (float*)d_out;
    float* o_mlp = out;
    float* o_ks  = out + (size_t)1 * SLOT;
    float* o_kc  = out + (size_t)3 * SLOT;

    cudaFuncSetAttribute(tc_gemm<2>, cudaFuncAttributeMaxDynamicSharedMemorySize, TC_SMEM_BYTES);
    cudaFuncSetAttribute(tc_gemm<3>, cudaFuncAttributeMaxDynamicSharedMemorySize, TC_SMEM_BYTES);
    cudaFuncSetAttribute(tc_gemm<4>, cudaFuncAttributeMaxDynamicSharedMemorySize, TC_SMEM_BYTES);
    cudaFuncSetAttribute(tc_gemm<5>, cudaFuncAttributeMaxDynamicSharedMemorySize, TC_SMEM_BYTES);
    cudaFuncSetAttribute(tc_gemm<6>, cudaFuncAttributeMaxDynamicSharedMemorySize, TC_SMEM_BYTES);
    cudaFuncSetAttribute(attn_tc<0>, cudaFuncAttributeMaxDynamicSharedMemorySize, ATT_SMEM0);
    cudaFuncSetAttribute(attn_tc<1>, cudaFuncAttributeMaxDynamicSharedMemorySize, ATT_SMEM1);

    // ---- preprocess ----
    {
        XP8 p;
        p.src[0] = wq_s; p.src[1] = wk_s; p.src[2] = wv_s; p.src[3] = wo_s;
        p.src[4] = wq_c; p.src[5] = wk_c; p.src[6] = wv_c; p.src[7] = wo_c;
        xpose_f16_b8<<<dim3(DD/32, DD/32, 8), dim3(32, 8)>>>(p, hw);
    }
    const dim3 xb(32, 8);
    xpose_f16<<<dim3(FF/32, DD/32), xb>>>(w1, tw1, DD, FF);
    xpose_f16<<<dim3(DD/32, FF/32), xb>>>(w2, tw2, FF, DD);
    f32_to_f16<<<(4*WSZ)/4/256, 256>>>((const float4*)memory, (__half2*)hmem);
    f32_to_f16<<<(16*WSZ)/4/256, 256>>>((const float4*)pos_emb, (__half2*)hbias);

    const dim3 gD(DD / 128, MTOT / 128);        // (8, 32)
    const dim3 gQKV(3 * DD / 128, MTOT / 128);  // (24, 32)
    const dim3 gKV(2 * DD / 128, MTOT / 128);   // (16, 32)
    const dim3 gF(FF / 128, MTOT / 128);        // (32, 32)
    const dim3 gA(LT / 64, HH, BB);

    // ---- self-attention block ----
    rmsnorm_kernel<<<MTOT, 256>>>(x, gamma_sa, (__half2*)bh);
    tc_gemm<5><<<gQKV, 256, TC_SMEM_BYTES>>>(bh, twq_s, o_ks, nullptr, hks, bq, MTOT, 3*DD, DD);
    attn_tc<0><<<gA, 128, ATT_SMEM0>>>(bq, hks, hks + (size_t)SLOT, nullptr, battn);
    tc_gemm<2><<<gD, 256, TC_SMEM_BYTES>>>(battn, two_s, bx1, x, nullptr, nullptr, MTOT, DD, DD);

    // ---- cross-attention block ----
    rmsnorm_kernel<<<MTOT, 256>>>(bx1, gamma_ca, (__half2*)bh);
    tc_gemm<4><<<gD, 256, TC_SMEM_BYTES>>>(bh,   twq_c, nullptr, nullptr, bq, nullptr, MTOT, DD, DD);
    tc_gemm<6><<<gKV, 256, TC_SMEM_BYTES>>>(hmem, twk_c, o_kc, nullptr, hkc, nullptr, MTOT, 2*DD, DD);
    attn_tc<1><<<gA, 128, ATT_SMEM1>>>(bq, hkc, hkc + (size_t)SLOT, hbias, battn);
    tc_gemm<2><<<gD, 256, TC_SMEM_BYTES>>>(battn, two_c, bx2, bx1, nullptr, nullptr, MTOT, DD, DD);

    // ---- FFN block ----
    rmsnorm_kernel<<<MTOT, 256>>>(bx2, gamma_m, (__half2*)bh);
    tc_gemm<3><<<gF, 256, TC_SMEM_BYTES>>>(bh,   tw1, nullptr, nullptr, bffn, nullptr, MTOT, FF, DD);
    tc_gemm<2><<<gD, 256, TC_SMEM_BYTES>>>(bffn, tw2, o_mlp, bx2, nullptr, nullptr, MTOT, DD, FF);
}